// round 12
// baseline (speedup 1.0000x reference)
#include <cuda_runtime.h>
#include <cuda_fp16.h>
#include <math.h>
#include <stdint.h>

typedef unsigned short u16;

// ---------------- problem constants ----------------
#define BATCH 32
#define IH 120
#define IW 640
#define OH1 90            // only rows 0..89 consumed by conv2
#define NCAP 3456
#define NCLS 5
#define FD 16
#define JD 80
#define NREL 25
#define K1 4800
#define K2 25600
#define NPOS 108
#define KSPLIT 8

// ---------------- device scratch ----------------
// B operand, fragment order: [(b*120+row)*10+slice][j 0..15][lane][2 u32]
__device__ uint32_t g_inf[(size_t)BATCH * IH * 10 * 1024];
// A operand, fragment order: [step*16+rb][lane][4 u32]
__device__ uint4 g_w1f[300 * 16 * 32];
__device__ u16 g_w2h[256 * K2];                  // conv2 W [c2][r*256+c1]
__device__ u16 g_c1[(size_t)BATCH * NPOS * K2];  // conv1 out [b][pos][r*256+c]
__device__ float g_prim4[KSPLIT][BATCH * 256 * NPOS];
__device__ float g_up[BATCH * NCAP * JD];
__device__ float g_bb[2][BATCH * NCAP * NCLS];
__device__ float g_v[2][BATCH * NCLS * FD];

// ---------------- helpers ----------------
__device__ __forceinline__ void mma16816(float* c, const uint32_t* a,
                                         const uint32_t* b) {
    asm volatile(
        "mma.sync.aligned.m16n8k16.row.col.f32.f16.f16.f32 "
        "{%0,%1,%2,%3}, {%4,%5,%6,%7}, {%8,%9}, {%0,%1,%2,%3};"
        : "+f"(c[0]), "+f"(c[1]), "+f"(c[2]), "+f"(c[3])
        : "r"(a[0]), "r"(a[1]), "r"(a[2]), "r"(a[3]), "r"(b[0]), "r"(b[1]));
}
__device__ __forceinline__ uint32_t pack2h(float v0, float v1) {
    __half2 h = __floats2half2_rn(v0, v1);
    return *(uint32_t*)&h;
}

// =====================================================================
// prep: input -> B fragment order.
// col0 = 4*(8*j+grp) + 16*sg + 2*tig + 8*w ; zero beyond width.
// =====================================================================
__global__ void prep_inf(const float* __restrict__ in,
                         uint32_t* __restrict__ inf) {
    size_t idx = (size_t)blockIdx.x * 256 + threadIdx.x;
    if (idx >= (size_t)BATCH * IH * 10 * 1024) return;
    int w = idx & 1;
    int lane = (idx >> 1) & 31;
    int j = (idx >> 6) & 15;
    size_t t = idx >> 10;
    int sg = (int)(t % 10);
    size_t rowb = t / 10;                  // b*IH + row
    int grp = lane >> 2, tig = lane & 3;
    int col0 = 4 * (8 * j + grp) + 16 * sg + 2 * tig + 8 * w;
    float v0 = (col0 < IW) ? in[rowb * IW + col0] : 0.0f;
    float v1 = (col0 + 1 < IW) ? in[rowb * IW + col0 + 1] : 0.0f;
    inf[idx] = pack2h(v0, v1);
}

// =====================================================================
// prep conv1 weights -> A fragment order.
// j: bit0 -> row+8, bit1 -> k+8.
// =====================================================================
__global__ void prep_c1wf(const float* __restrict__ w,
                          uint32_t* __restrict__ w1f) {
    int idx = blockIdx.x * 256 + threadIdx.x;   // u32 index, 614400 total
    if (idx >= 300 * 16 * 32 * 4) return;
    int j = idx & 3;
    int lane = (idx >> 2) & 31;
    int rb = (idx >> 7) & 15;
    int step = idx >> 11;
    int grp = lane >> 2, tig = lane & 3;
    int c = rb * 16 + grp + (j & 1) * 8;
    int kk = 2 * tig + (j >> 1) * 8;
    int kh = step / 10, kws = step - 10 * kh;
    int kg = kh * 160 + kws * 16 + kk;
    w1f[idx] = pack2h(w[(size_t)c * K1 + kg], w[(size_t)c * K1 + kg + 1]);
}

// =====================================================================
// prep conv2 weights: (256,256,10,10) -> [c2][r*256+c1] fp16
// =====================================================================
__global__ void prep_c2w(const float* __restrict__ w2, u16* __restrict__ wh) {
    int idx = blockIdx.x * 256 + threadIdx.x;
    if (idx >= 256 * K2) return;
    int c2 = idx / K2;
    int k = idx - c2 * K2;
    int r = k >> 8, c1 = k & 255;
    wh[idx] = __half_as_ushort(
        __float2half_rn(w2[(size_t)(c2 * 256 + c1) * 100 + r]));
}

// =====================================================================
// conv1 via HMMA, pure fp16, fragment-order operands, ZERO smem/sync.
// CTA = (mt, oh, b): M128 x N128(ow) x K4800.
// 8 warps 2(M)x4(N), warp tile 64x32, 2 CTAs/SM.
// A and B fragments both direct LDG from fragment-order gmem
// (A: 1x LDG.128 per frag, L2-resident; B: 1x LDG.64 per frag).
// No barriers at all -- warps are fully independent.
// =====================================================================
__global__ __launch_bounds__(256, 2)
void conv1_mma(const uint32_t* __restrict__ inf, const uint4* __restrict__ w1f,
               const float* __restrict__ bias, u16* __restrict__ c1) {
    const int tid = threadIdx.x;
    const int wid = tid >> 5, lane = tid & 31;
    const int grp = lane >> 2, tig = lane & 3;
    const int wm = wid >> 2, wn = wid & 3;
    const int mt = blockIdx.x, oh = blockIdx.y, b = blockIdx.z;

    float acc[4][4][4] = {};

    // A: fragment (step, rb=mt*8 + wm*4 + mf) at lane
    const uint4* Ab = w1f + (size_t)(mt * 8 + wm * 4) * 32 + lane;
    // B: row (b*IH + oh + kh), slice s, quarter wn, lane
    const uint32_t* Bb = inf + ((size_t)b * IH + oh) * 10240 + wn * 256 +
                         lane * 2;

    for (int kh = 0; kh < 30; ++kh) {
        const uint32_t* br = Bb + (size_t)kh * 10240;
        const uint4* ar = Ab + (size_t)kh * 10 * 16 * 32;
#pragma unroll 2
        for (int s = 0; s < 10; ++s) {
            uint2 bf[4];
#pragma unroll
            for (int nf = 0; nf < 4; ++nf)
                bf[nf] = *(const uint2*)(br + s * 1024 + nf * 64);
            uint4 af[4];
#pragma unroll
            for (int mf = 0; mf < 4; ++mf)
                af[mf] = ar[(s * 16 + mf) * 32];
#pragma unroll
            for (int mf = 0; mf < 4; ++mf)
#pragma unroll
                for (int nf = 0; nf < 4; ++nf)
                    mma16816(acc[mf][nf], (const uint32_t*)&af[mf],
                             (const uint32_t*)&bf[nf]);
        }
    }

    // epilogue: bias + relu -> fp16, conv2 im2col order
    const int ohh = oh / 10, kh2 = oh - 10 * ohh;
#pragma unroll
    for (int mf = 0; mf < 4; ++mf) {
#pragma unroll
        for (int nf = 0; nf < 4; ++nf) {
#pragma unroll
            for (int i = 0; i < 4; ++i) {
                const int c = mt * 128 + wm * 64 + mf * 16 + grp + (i >> 1) * 8;
                const int ow = wn * 32 + nf * 8 + 2 * tig + (i & 1);
                if (ow < 120) {
                    float v = fmaxf(acc[mf][nf][i] + bias[c], 0.0f);
                    int pos = ohh * 12 + ow / 10;
                    int r = kh2 * 10 + (ow % 10);
                    c1[(((size_t)b * NPOS + pos) * 100 + r) * 256 + c] =
                        __half_as_ushort(__float2half_rn(v));
                }
            }
        }
    }
}

// =====================================================================
// conv2 via HMMA, pure fp16: GEMM M=256 x N=108 x K=25600, 8-way K split.
// =====================================================================
__global__ __launch_bounds__(256, 2)
void conv2_mma(const u16* __restrict__ c1, const u16* __restrict__ w2h,
               const float* __restrict__ pb, float* __restrict__ prim4) {
    __shared__ u16 s_A[128 * 16];
    __shared__ u16 s_B[128 * 16];

    const int tid = threadIdx.x;
    const int wid = tid >> 5, lane = tid & 31;
    const int grp = lane >> 2, tig = lane & 3;
    const int msub = wid & 1, nsub = wid >> 1;
    const int mt = blockIdx.x, b = blockIdx.y, ks = blockIdx.z;

    float acc[4][4][4] = {};

    const int ar = tid >> 1, ah8 = (tid & 1) * 8;
    const u16* Ap = w2h + (size_t)(mt * 128 + ar) * K2 + ah8;
    const u16* Bp = c1 + ((size_t)b * NPOS + ar) * K2 + ah8;
    const bool bvalid = ar < NPOS;

    const int kbase = ks * (K2 / KSPLIT);
    const int NSTEP = K2 / KSPLIT / 16;              // 200
    uint4 z = make_uint4(0, 0, 0, 0);
    uint4 rA = *(const uint4*)(Ap + kbase);
    uint4 rB = bvalid ? *(const uint4*)(Bp + kbase) : z;

    for (int s = 0; s < NSTEP; ++s) {
        __syncthreads();
        *(uint4*)(s_A + ar * 16 + ah8) = rA;
        *(uint4*)(s_B + ar * 16 + ah8) = rB;
        __syncthreads();
        if (s < NSTEP - 1) {
            const int k = kbase + (s + 1) * 16;
            rA = *(const uint4*)(Ap + k);
            rB = bvalid ? *(const uint4*)(Bp + k) : z;
        }
        uint32_t bf[4][2];
#pragma unroll
        for (int nf = 0; nf < 4; ++nf) {
            int n0 = (nsub * 32 + nf * 8 + grp) * 16 + 2 * tig;
            bf[nf][0] = *(const uint32_t*)(s_B + n0);
            bf[nf][1] = *(const uint32_t*)(s_B + n0 + 8);
        }
#pragma unroll
        for (int mf = 0; mf < 4; ++mf) {
            const int m0 = msub * 64 + mf * 16;
            uint32_t a_h[4];
            a_h[0] = *(const uint32_t*)(s_A + (m0 + grp) * 16 + 2 * tig);
            a_h[1] = *(const uint32_t*)(s_A + (m0 + grp + 8) * 16 + 2 * tig);
            a_h[2] = *(const uint32_t*)(s_A + (m0 + grp) * 16 + 2 * tig + 8);
            a_h[3] = *(const uint32_t*)(s_A + (m0 + grp + 8) * 16 + 2 * tig + 8);
#pragma unroll
            for (int nf = 0; nf < 4; ++nf)
                mma16816(acc[mf][nf], a_h, bf[nf]);
        }
    }

    float* outp = prim4 + (size_t)ks * (BATCH * 256 * NPOS);
#pragma unroll
    for (int mf = 0; mf < 4; ++mf) {
#pragma unroll
        for (int nf = 0; nf < 4; ++nf) {
#pragma unroll
            for (int i = 0; i < 4; ++i) {
                const int c2 = mt * 128 + msub * 64 + mf * 16 + grp + (i >> 1) * 8;
                const int n = nsub * 32 + nf * 8 + 2 * tig + (i & 1);
                if (n < NPOS) {
                    float v = acc[mf][nf][i] + (ks == 0 ? pb[c2] : 0.0f);
                    outp[((size_t)b * 256 + c2) * NPOS + n] = v;
                }
            }
        }
    }
}

// =====================================================================
// squash + caps prediction (sums KSPLIT conv2 partials)
// =====================================================================
__global__ void squash_predict_kernel(const float* __restrict__ prim4,
                                      const float* __restrict__ caps_w,
                                      float* __restrict__ up) {
    __shared__ float su[8];
    __shared__ float sfac;
    const int i = blockIdx.x;
    const int b = blockIdx.y;
    const int g = i / NPOS;
    const int p = i - g * NPOS;
    const int t = threadIdx.x;
    const int SL = BATCH * 256 * NPOS;

    if (t < 8) {
        size_t o = ((size_t)b * 256 + g * 8 + t) * NPOS + p;
        float acc = 0.0f;
#pragma unroll
        for (int q = 0; q < KSPLIT; ++q) acc += prim4[o + (size_t)q * SL];
        su[t] = acc;
    }
    __syncthreads();
    if (t == 0) {
        float l2 = 0.0f;
#pragma unroll
        for (int d = 0; d < 8; ++d) l2 += su[d] * su[d];
        sfac = sqrtf(l2) / (1.0f + l2);
    }
    __syncthreads();
    const float f = sfac;
    const float* cw = caps_w + (size_t)i * 8 * JD + t;
    float a = 0.0f;
#pragma unroll
    for (int d = 0; d < 8; ++d) a += su[d] * f * cw[d * JD];
    up[((size_t)b * NCAP + i) * JD + t] = a;
}

// =====================================================================
// routing iteration 0
// =====================================================================
__global__ void route_s0_kernel(const float* __restrict__ up,
                                const float* __restrict__ b_route,
                                float* __restrict__ vout) {
    const int o = blockIdx.x;
    const int b = blockIdx.y;
    const int t = threadIdx.x;
    const int lane = t & 31, wid = t >> 5;

    float sd[FD];
#pragma unroll
    for (int d = 0; d < FD; ++d) sd[d] = 0.0f;

    for (int i = t; i < NCAP; i += 256) {
        float br[NCLS];
#pragma unroll
        for (int oo = 0; oo < NCLS; ++oo) br[oo] = b_route[i * NCLS + oo];
        float m = br[0];
#pragma unroll
        for (int oo = 1; oo < NCLS; ++oo) m = fmaxf(m, br[oo]);
        float s = 0.0f;
#pragma unroll
        for (int oo = 0; oo < NCLS; ++oo) s += expf(br[oo] - m);
        float ci = expf(br[o] - m) / s;
        const float* u = up + ((size_t)b * NCAP + i) * JD + o * FD;
#pragma unroll
        for (int d = 0; d < FD; ++d) sd[d] += ci * u[d];
    }
#pragma unroll
    for (int d = 0; d < FD; ++d)
        for (int off = 16; off; off >>= 1)
            sd[d] += __shfl_down_sync(0xffffffffu, sd[d], off);

    __shared__ float part[8][FD];
    __shared__ float fin[FD];
    __shared__ float fac;
    if (lane == 0)
#pragma unroll
        for (int d = 0; d < FD; ++d) part[wid][d] = sd[d];
    __syncthreads();
    if (t < FD) {
        float tot = 0.0f;
#pragma unroll
        for (int ww = 0; ww < 8; ++ww) tot += part[ww][t];
        fin[t] = tot;
    }
    __syncthreads();
    if (t == 0) {
        float l2 = 0.0f;
#pragma unroll
        for (int d = 0; d < FD; ++d) l2 += fin[d] * fin[d];
        fac = sqrtf(l2) / (1.0f + l2);
    }
    __syncthreads();
    if (t < FD) vout[((size_t)b * NCLS + o) * FD + t] = fin[t] * fac;
}

// =====================================================================
// fused routing iteration (double-buffered bb and v)
// =====================================================================
__global__ void route_fused(const float* __restrict__ up,
                            const float* __restrict__ b_route,
                            const float* __restrict__ vin,
                            float* __restrict__ vout,
                            const float* __restrict__ bb_rd,
                            float* __restrict__ bb_wr, int first) {
    const int o = blockIdx.x;
    const int b = blockIdx.y;
    const int t = threadIdx.x;
    const int lane = t & 31, wid = t >> 5;

    __shared__ float sv[JD];
    if (t < JD) sv[t] = vin[b * JD + t];
    __syncthreads();

    float sd[FD];
#pragma unroll
    for (int d = 0; d < FD; ++d) sd[d] = 0.0f;

    for (int i = t; i < NCAP; i += 256) {
        const size_t base = ((size_t)b * NCAP + i);
        float u[JD];
        const float4* u4 = (const float4*)(up + base * JD);
#pragma unroll
        for (int q = 0; q < JD / 4; ++q) {
            float4 vv = u4[q];
            u[4 * q] = vv.x; u[4 * q + 1] = vv.y;
            u[4 * q + 2] = vv.z; u[4 * q + 3] = vv.w;
        }
        float nb[NCLS];
#pragma unroll
        for (int oo = 0; oo < NCLS; ++oo) {
            float dot = 0.0f;
#pragma unroll
            for (int d = 0; d < FD; ++d) dot += u[oo * FD + d] * sv[oo * FD + d];
            float prev = first ? b_route[i * NCLS + oo] : bb_rd[base * NCLS + oo];
            nb[oo] = prev + dot;
        }
        if (o == 0) {
#pragma unroll
            for (int oo = 0; oo < NCLS; ++oo) bb_wr[base * NCLS + oo] = nb[oo];
        }
        float m = nb[0];
#pragma unroll
        for (int oo = 1; oo < NCLS; ++oo) m = fmaxf(m, nb[oo]);
        float s = 0.0f;
#pragma unroll
        for (int oo = 0; oo < NCLS; ++oo) s += expf(nb[oo] - m);
        float ci = expf(nb[o] - m) / s;
#pragma unroll
        for (int d = 0; d < FD; ++d) sd[d] += ci * u[o * FD + d];
    }
#pragma unroll
    for (int d = 0; d < FD; ++d)
        for (int off = 16; off; off >>= 1)
            sd[d] += __shfl_down_sync(0xffffffffu, sd[d], off);

    __shared__ float part[8][FD];
    __shared__ float fin[FD];
    __shared__ float fac;
    if (lane == 0)
#pragma unroll
        for (int d = 0; d < FD; ++d) part[wid][d] = sd[d];
    __syncthreads();
    if (t < FD) {
        float tot = 0.0f;
#pragma unroll
        for (int ww = 0; ww < 8; ++ww) tot += part[ww][t];
        fin[t] = tot;
    }
    __syncthreads();
    if (t == 0) {
        float l2 = 0.0f;
#pragma unroll
        for (int d = 0; d < FD; ++d) l2 += fin[d] * fin[d];
        fac = sqrtf(l2) / (1.0f + l2);
    }
    __syncthreads();
    if (t < FD) vout[((size_t)b * NCLS + o) * FD + t] = fin[t] * fac;
}

// =====================================================================
// heads
// =====================================================================
__global__ void head_kernel(const float* __restrict__ v,
                            const float* __restrict__ pred_w,
                            const float* __restrict__ pred_b,
                            const float* __restrict__ eos_w,
                            const float* __restrict__ eos_b,
                            float* __restrict__ out) {
    const int t = threadIdx.x;
    if (t >= BATCH * NCLS) return;
    const float* vv = v + (size_t)t * FD;
    float lg[NREL + 1];
#pragma unroll 4
    for (int r = 0; r < NREL; ++r) {
        float a = pred_b[r];
#pragma unroll
        for (int d = 0; d < FD; ++d) a += vv[d] * pred_w[r * FD + d];
        lg[r] = a;
    }
    {
        float a = eos_b[0];
#pragma unroll
        for (int d = 0; d < FD; ++d) a += vv[d] * eos_w[d];
        lg[NREL] = a;
    }
    float m = lg[0];
#pragma unroll
    for (int k = 1; k <= NREL; ++k) m = fmaxf(m, lg[k]);
    float s = 0.0f;
#pragma unroll
    for (int k = 0; k <= NREL; ++k) s += expf(lg[k] - m);
    const float ls = m + logf(s);
#pragma unroll
    for (int k = 0; k <= NREL; ++k) out[(size_t)t * (NREL + 1) + k] = lg[k] - ls;
}

// =====================================================================
extern "C" void kernel_launch(void* const* d_in, const int* in_sizes, int n_in,
                              void* d_out, int out_size) {
    const float* input   = (const float*)d_in[0];
    const float* conv1_w = (const float*)d_in[1];
    const float* conv1_b = (const float*)d_in[2];
    const float* prim_w  = (const float*)d_in[3];
    const float* prim_b  = (const float*)d_in[4];
    const float* caps_w  = (const float*)d_in[5];
    const float* b_route = (const float*)d_in[6];
    const float* pred_w  = (const float*)d_in[7];
    const float* pred_b  = (const float*)d_in[8];
    const float* eos_w   = (const float*)d_in[9];
    const float* eos_b   = (const float*)d_in[10];
    float* out = (float*)d_out;

    uint32_t* infp;
    uint4* w1fp;
    u16 *w2h, *c1;
    float *prim4, *upp, *bbp, *vp;
    cudaGetSymbolAddress((void**)&infp, g_inf);
    cudaGetSymbolAddress((void**)&w1fp, g_w1f);
    cudaGetSymbolAddress((void**)&w2h, g_w2h);
    cudaGetSymbolAddress((void**)&c1, g_c1);
    cudaGetSymbolAddress((void**)&prim4, g_prim4);
    cudaGetSymbolAddress((void**)&upp, g_up);
    cudaGetSymbolAddress((void**)&bbp, g_bb);
    cudaGetSymbolAddress((void**)&vp, g_v);

    const int NBB = BATCH * NCAP * NCLS;
    const int NV = BATCH * NCLS * FD;
    const size_t NINF = (size_t)BATCH * IH * 10 * 1024;

    prep_inf<<<(unsigned)((NINF + 255) / 256), 256>>>(input, infp);
    prep_c1wf<<<(300 * 16 * 32 * 4 + 255) / 256, 256>>>(conv1_w,
                                                        (uint32_t*)w1fp);
    prep_c2w<<<(256 * K2 + 255) / 256, 256>>>(prim_w, w2h);
    conv1_mma<<<dim3(2, OH1, BATCH), 256>>>(infp, w1fp, conv1_b, c1);
    conv2_mma<<<dim3(2, BATCH, KSPLIT), 256>>>(c1, w2h, prim_b, prim4);
    squash_predict_kernel<<<dim3(NCAP, BATCH), 80>>>(prim4, caps_w, upp);
    route_s0_kernel<<<dim3(NCLS, BATCH), 256>>>(upp, b_route, vp);
    route_fused<<<dim3(NCLS, BATCH), 256>>>(upp, b_route, vp, vp + NV,
                                            bbp, bbp, 1);
    route_fused<<<dim3(NCLS, BATCH), 256>>>(upp, b_route, vp + NV, vp,
                                            bbp, bbp + NBB, 0);
    route_fused<<<dim3(NCLS, BATCH), 256>>>(upp, b_route, vp, vp + NV,
                                            bbp + NBB, bbp, 0);
    head_kernel<<<1, BATCH * NCLS>>>(vp + NV, pred_w, pred_b, eos_w, eos_b, out);
}

// round 13
// speedup vs baseline: 1.1091x; 1.1091x over previous
#include <cuda_runtime.h>
#include <cuda_fp16.h>
#include <math.h>
#include <stdint.h>

typedef unsigned short u16;

// ---------------- problem constants ----------------
#define BATCH 32
#define IH 120
#define IW 640
#define OH1 90            // only rows 0..89 consumed by conv2
#define NCAP 3456
#define NCLS 5
#define FD 16
#define JD 80
#define NREL 25
#define K1 4800
#define K2 25600
#define NPOS 108
#define KSPLIT 8
#define NS2 1600          // K2/16 k16-slices

// ---------------- device scratch ----------------
// conv1 B operand, fragment order: [(b*120+row)*10+slice][j 0..15][lane][2u32]
__device__ uint32_t g_inf[(size_t)BATCH * IH * 10 * 1024];
// conv1 A operand, fragment order: [step*16+rb][lane][4 u32]
__device__ uint4 g_w1f[300 * 16 * 32];
// conv2 A operand, fragment order: [s2*16+rb][lane][4 u32]
__device__ uint4 g_w2f[NS2 * 16 * 32];
// conv2 B operand (conv1 output), fragment order: [b][s2][nf 0..15][lane][2u32]
__device__ uint32_t g_bf2[(size_t)BATCH * NS2 * 16 * 64];
__device__ float g_prim4[KSPLIT][BATCH * 256 * NPOS];
__device__ float g_up[BATCH * NCAP * JD];
__device__ float g_bb[2][BATCH * NCAP * NCLS];
__device__ float g_v[2][BATCH * NCLS * FD];

// ---------------- helpers ----------------
__device__ __forceinline__ void mma16816(float* c, const uint32_t* a,
                                         const uint32_t* b) {
    asm volatile(
        "mma.sync.aligned.m16n8k16.row.col.f32.f16.f16.f32 "
        "{%0,%1,%2,%3}, {%4,%5,%6,%7}, {%8,%9}, {%0,%1,%2,%3};"
        : "+f"(c[0]), "+f"(c[1]), "+f"(c[2]), "+f"(c[3])
        : "r"(a[0]), "r"(a[1]), "r"(a[2]), "r"(a[3]), "r"(b[0]), "r"(b[1]));
}
__device__ __forceinline__ void cp16(uint32_t dst, const void* src) {
    asm volatile("cp.async.ca.shared.global [%0], [%1], 16;"
                 :: "r"(dst), "l"(src));
}
__device__ __forceinline__ void cp_commit() {
    asm volatile("cp.async.commit_group;");
}
__device__ __forceinline__ void cp_wait0() {
    asm volatile("cp.async.wait_group 0;");
}
__device__ __forceinline__ uint32_t pack2h(float v0, float v1) {
    __half2 h = __floats2half2_rn(v0, v1);
    return *(uint32_t*)&h;
}

// =====================================================================
// prep: input -> conv1 B fragment order.
// =====================================================================
__global__ void prep_inf(const float* __restrict__ in,
                         uint32_t* __restrict__ inf) {
    size_t idx = (size_t)blockIdx.x * 256 + threadIdx.x;
    if (idx >= (size_t)BATCH * IH * 10 * 1024) return;
    int w = idx & 1;
    int lane = (idx >> 1) & 31;
    int j = (idx >> 6) & 15;
    size_t t = idx >> 10;
    int sg = (int)(t % 10);
    size_t rowb = t / 10;
    int grp = lane >> 2, tig = lane & 3;
    int col0 = 4 * (8 * j + grp) + 16 * sg + 2 * tig + 8 * w;
    float v0 = (col0 < IW) ? in[rowb * IW + col0] : 0.0f;
    float v1 = (col0 + 1 < IW) ? in[rowb * IW + col0 + 1] : 0.0f;
    inf[idx] = pack2h(v0, v1);
}

// =====================================================================
// prep conv1 weights -> A fragment order.
// =====================================================================
__global__ void prep_c1wf(const float* __restrict__ w,
                          uint32_t* __restrict__ w1f) {
    int idx = blockIdx.x * 256 + threadIdx.x;   // 614400
    if (idx >= 300 * 16 * 32 * 4) return;
    int j = idx & 3;
    int lane = (idx >> 2) & 31;
    int rb = (idx >> 7) & 15;
    int step = idx >> 11;
    int grp = lane >> 2, tig = lane & 3;
    int c = rb * 16 + grp + (j & 1) * 8;
    int kk = 2 * tig + (j >> 1) * 8;
    int kh = step / 10, kws = step - 10 * kh;
    int kg = kh * 160 + kws * 16 + kk;
    w1f[idx] = pack2h(w[(size_t)c * K1 + kg], w[(size_t)c * K1 + kg + 1]);
}

// =====================================================================
// prep conv2 weights -> A fragment order [s2][rb][lane][j].
// k-order: k = r*256 + c1, r = kh*10+kw.
// =====================================================================
__global__ void prep_c2wf(const float* __restrict__ w2,
                          uint32_t* __restrict__ w2f) {
    int idx = blockIdx.x * 256 + threadIdx.x;   // 3,276,800
    if (idx >= NS2 * 16 * 32 * 4) return;
    int j = idx & 3;
    int lane = (idx >> 2) & 31;
    int rb = (idx >> 7) & 15;
    int s2 = idx >> 11;
    int grp = lane >> 2, tig = lane & 3;
    int c2 = rb * 16 + grp + (j & 1) * 8;
    int k0 = s2 * 16 + 2 * tig + (j >> 1) * 8;
    float v0 = w2[((size_t)c2 * 256 + (k0 & 255)) * 100 + (k0 >> 8)];
    float v1 = w2[((size_t)c2 * 256 + ((k0 + 1) & 255)) * 100 + ((k0 + 1) >> 8)];
    w2f[idx] = pack2h(v0, v1);
}

// =====================================================================
// conv1 via HMMA, pure fp16, fragment-order operands (R11 structure).
// CTA = (mt, oh, b): M128 x N128(ow) x K4800. 8 warps 2(M)x4(N),
// warp 64x32, 2 CTAs/SM. A: full kh-row per cp.async stage (80KB dyn
// smem, 30 syncs). B: direct LDG.64.
// Epilogue: bias+relu -> fp16 written DIRECTLY in conv2-B-fragment order.
// =====================================================================
__global__ __launch_bounds__(256, 2)
void conv1_mma(const uint32_t* __restrict__ inf, const uint4* __restrict__ w1f,
               const float* __restrict__ bias, u16* __restrict__ bf2) {
    extern __shared__ uint4 sA[];   // [2][2560]

    const int tid = threadIdx.x;
    const int wid = tid >> 5, lane = tid & 31;
    const int grp = lane >> 2, tig = lane & 3;
    const int wm = wid >> 2, wn = wid & 3;
    const int mt = blockIdx.x, oh = blockIdx.y, b = blockIdx.z;

    float acc[4][4][4] = {};

    const uint32_t sA0 = (uint32_t)__cvta_generic_to_shared(&sA[0]);

    auto stageA = [&](int it, int stg) {
#pragma unroll
        for (int r = 0; r < 10; ++r) {
            const int c = tid + (r << 8);
            const int slice = c >> 8;
            const int rbl = (c >> 5) & 7;
            const int ln = c & 31;
            const int step = it * 10 + slice;
            cp16(sA0 + (stg * 2560 + c) * 16,
                 w1f + ((step * 16 + mt * 8 + rbl) * 32 + ln));
        }
        cp_commit();
    };

    stageA(0, 0);
    cp_wait0();
    __syncthreads();

    for (int it = 0; it < 30; ++it) {                  // it = kh
        const int stg = it & 1;
        if (it < 29) stageA(it + 1, stg ^ 1);

        const size_t rowb = (size_t)b * IH + oh + it;
        const uint32_t* bb = inf + rowb * 10240 + wn * 256 + lane * 2;
#pragma unroll
        for (int s = 0; s < 10; ++s) {
            uint2 bf[4];
#pragma unroll
            for (int nf = 0; nf < 4; ++nf)
                bf[nf] = *(const uint2*)(bb + s * 1024 + nf * 64);
            uint4 af[4];
#pragma unroll
            for (int mf = 0; mf < 4; ++mf)
                af[mf] = sA[stg * 2560 + s * 256 + (wm * 4 + mf) * 32 + lane];
#pragma unroll
            for (int mf = 0; mf < 4; ++mf)
#pragma unroll
                for (int nf = 0; nf < 4; ++nf)
                    mma16816(acc[mf][nf], (const uint32_t*)&af[mf],
                             (const uint32_t*)&bf[nf]);
        }
        cp_wait0();
        __syncthreads();
    }

    // epilogue: bias + relu -> fp16, conv2-B-fragment order.
    // element: c = mt*128+wm*64+mf*16+grp+(i>>1)*8, ow = wn*32+nf*8+2tig+(i&1)
    // k = r*256+c -> s2 = r*16 + mt*8+wm*4+mf, kk = grp+8*(i>>1)
    // B-frag: lane2 = (pos&7)*4 + (grp>>1), word = i>>1, half = grp&1
    const int ohh = oh / 10, kh2 = oh - 10 * ohh;
#pragma unroll
    for (int mf = 0; mf < 4; ++mf) {
#pragma unroll
        for (int nf = 0; nf < 4; ++nf) {
#pragma unroll
            for (int i = 0; i < 4; ++i) {
                const int c = mt * 128 + wm * 64 + mf * 16 + grp + (i >> 1) * 8;
                const int ow = wn * 32 + nf * 8 + 2 * tig + (i & 1);
                if (ow < 120) {
                    float v = fmaxf(acc[mf][nf][i] + bias[c], 0.0f);
                    const int pos = ohh * 12 + ow / 10;
                    const int r = kh2 * 10 + (ow % 10);
                    const int s2 = r * 16 + mt * 8 + wm * 4 + mf;
                    const int lane2 = (pos & 7) * 4 + (grp >> 1);
                    const size_t o =
                        ((((size_t)b * NS2 + s2) * 16 + (pos >> 3)) * 32 +
                         lane2) * 4 + (i >> 1) * 2 + (grp & 1);
                    bf2[o] = __half_as_ushort(__float2half_rn(v));
                }
            }
        }
    }
}

// =====================================================================
// conv2 via HMMA, barrier-free fragment-order: M=256(mt 2) x N=128(pad)
// x K=25600, 8-way K split. grid (2, 32, 8). Warp 64x32, 2 CTAs/SM.
// n >= 108 columns are garbage (never written) and discarded at store.
// =====================================================================
__global__ __launch_bounds__(256, 2)
void conv2_mma(const uint32_t* __restrict__ bf2, const uint4* __restrict__ w2f,
               const float* __restrict__ pb, float* __restrict__ prim4) {
    const int tid = threadIdx.x;
    const int wid = tid >> 5, lane = tid & 31;
    const int grp = lane >> 2, tig = lane & 3;
    const int wm = wid >> 2, wn = wid & 3;
    const int mt = blockIdx.x, b = blockIdx.y, ks = blockIdx.z;

    float acc[4][4][4] = {};

    const int NSL = NS2 / KSPLIT;   // 200 slices per split
    const uint4* Ab = w2f + ((size_t)(ks * NSL) * 16 + mt * 8 + wm * 4) * 32 +
                      lane;
    const uint32_t* Bb = bf2 + (((size_t)b * NS2 + ks * NSL) * 16 + wn * 4) *
                         64 + lane * 2;

    for (int s = 0; s < NSL; ++s) {
        uint2 bfr[4];
#pragma unroll
        for (int nf = 0; nf < 4; ++nf)
            bfr[nf] = *(const uint2*)(Bb + (size_t)s * 1024 + nf * 64);
        uint4 af[4];
#pragma unroll
        for (int mf = 0; mf < 4; ++mf)
            af[mf] = Ab[((size_t)s * 16 + mf) * 32];
#pragma unroll
        for (int mf = 0; mf < 4; ++mf)
#pragma unroll
            for (int nf = 0; nf < 4; ++nf)
                mma16816(acc[mf][nf], (const uint32_t*)&af[mf],
                         (const uint32_t*)&bfr[nf]);
    }

    float* outp = prim4 + (size_t)ks * (BATCH * 256 * NPOS);
#pragma unroll
    for (int mf = 0; mf < 4; ++mf) {
#pragma unroll
        for (int nf = 0; nf < 4; ++nf) {
#pragma unroll
            for (int i = 0; i < 4; ++i) {
                const int c2 = mt * 128 + wm * 64 + mf * 16 + grp + (i >> 1) * 8;
                const int n = (wn * 4 + nf) * 8 + 2 * tig + (i & 1);
                if (n < NPOS) {
                    float v = acc[mf][nf][i] + (ks == 0 ? pb[c2] : 0.0f);
                    outp[((size_t)b * 256 + c2) * NPOS + n] = v;
                }
            }
        }
    }
}

// =====================================================================
// squash + caps prediction (sums KSPLIT conv2 partials)
// =====================================================================
__global__ void squash_predict_kernel(const float* __restrict__ prim4,
                                      const float* __restrict__ caps_w,
                                      float* __restrict__ up) {
    __shared__ float su[8];
    __shared__ float sfac;
    const int i = blockIdx.x;
    const int b = blockIdx.y;
    const int g = i / NPOS;
    const int p = i - g * NPOS;
    const int t = threadIdx.x;
    const int SL = BATCH * 256 * NPOS;

    if (t < 8) {
        size_t o = ((size_t)b * 256 + g * 8 + t) * NPOS + p;
        float acc = 0.0f;
#pragma unroll
        for (int q = 0; q < KSPLIT; ++q) acc += prim4[o + (size_t)q * SL];
        su[t] = acc;
    }
    __syncthreads();
    if (t == 0) {
        float l2 = 0.0f;
#pragma unroll
        for (int d = 0; d < 8; ++d) l2 += su[d] * su[d];
        sfac = sqrtf(l2) / (1.0f + l2);
    }
    __syncthreads();
    const float f = sfac;
    const float* cw = caps_w + (size_t)i * 8 * JD + t;
    float a = 0.0f;
#pragma unroll
    for (int d = 0; d < 8; ++d) a += su[d] * f * cw[d * JD];
    up[((size_t)b * NCAP + i) * JD + t] = a;
}

// =====================================================================
// routing iteration 0
// =====================================================================
__global__ void route_s0_kernel(const float* __restrict__ up,
                                const float* __restrict__ b_route,
                                float* __restrict__ vout) {
    const int o = blockIdx.x;
    const int b = blockIdx.y;
    const int t = threadIdx.x;
    const int lane = t & 31, wid = t >> 5;

    float sd[FD];
#pragma unroll
    for (int d = 0; d < FD; ++d) sd[d] = 0.0f;

    for (int i = t; i < NCAP; i += 256) {
        float br[NCLS];
#pragma unroll
        for (int oo = 0; oo < NCLS; ++oo) br[oo] = b_route[i * NCLS + oo];
        float m = br[0];
#pragma unroll
        for (int oo = 1; oo < NCLS; ++oo) m = fmaxf(m, br[oo]);
        float s = 0.0f;
#pragma unroll
        for (int oo = 0; oo < NCLS; ++oo) s += expf(br[oo] - m);
        float ci = expf(br[o] - m) / s;
        const float* u = up + ((size_t)b * NCAP + i) * JD + o * FD;
#pragma unroll
        for (int d = 0; d < FD; ++d) sd[d] += ci * u[d];
    }
#pragma unroll
    for (int d = 0; d < FD; ++d)
        for (int off = 16; off; off >>= 1)
            sd[d] += __shfl_down_sync(0xffffffffu, sd[d], off);

    __shared__ float part[8][FD];
    __shared__ float fin[FD];
    __shared__ float fac;
    if (lane == 0)
#pragma unroll
        for (int d = 0; d < FD; ++d) part[wid][d] = sd[d];
    __syncthreads();
    if (t < FD) {
        float tot = 0.0f;
#pragma unroll
        for (int ww = 0; ww < 8; ++ww) tot += part[ww][t];
        fin[t] = tot;
    }
    __syncthreads();
    if (t == 0) {
        float l2 = 0.0f;
#pragma unroll
        for (int d = 0; d < FD; ++d) l2 += fin[d] * fin[d];
        fac = sqrtf(l2) / (1.0f + l2);
    }
    __syncthreads();
    if (t < FD) vout[((size_t)b * NCLS + o) * FD + t] = fin[t] * fac;
}

// =====================================================================
// fused routing iteration (double-buffered bb and v)
// =====================================================================
__global__ void route_fused(const float* __restrict__ up,
                            const float* __restrict__ b_route,
                            const float* __restrict__ vin,
                            float* __restrict__ vout,
                            const float* __restrict__ bb_rd,
                            float* __restrict__ bb_wr, int first) {
    const int o = blockIdx.x;
    const int b = blockIdx.y;
    const int t = threadIdx.x;
    const int lane = t & 31, wid = t >> 5;

    __shared__ float sv[JD];
    if (t < JD) sv[t] = vin[b * JD + t];
    __syncthreads();

    float sd[FD];
#pragma unroll
    for (int d = 0; d < FD; ++d) sd[d] = 0.0f;

    for (int i = t; i < NCAP; i += 256) {
        const size_t base = ((size_t)b * NCAP + i);
        float u[JD];
        const float4* u4 = (const float4*)(up + base * JD);
#pragma unroll
        for (int q = 0; q < JD / 4; ++q) {
            float4 vv = u4[q];
            u[4 * q] = vv.x; u[4 * q + 1] = vv.y;
            u[4 * q + 2] = vv.z; u[4 * q + 3] = vv.w;
        }
        float nb[NCLS];
#pragma unroll
        for (int oo = 0; oo < NCLS; ++oo) {
            float dot = 0.0f;
#pragma unroll
            for (int d = 0; d < FD; ++d) dot += u[oo * FD + d] * sv[oo * FD + d];
            float prev = first ? b_route[i * NCLS + oo] : bb_rd[base * NCLS + oo];
            nb[oo] = prev + dot;
        }
        if (o == 0) {
#pragma unroll
            for (int oo = 0; oo < NCLS; ++oo) bb_wr[base * NCLS + oo] = nb[oo];
        }
        float m = nb[0];
#pragma unroll
        for (int oo = 1; oo < NCLS; ++oo) m = fmaxf(m, nb[oo]);
        float s = 0.0f;
#pragma unroll
        for (int oo = 0; oo < NCLS; ++oo) s += expf(nb[oo] - m);
        float ci = expf(nb[o] - m) / s;
#pragma unroll
        for (int d = 0; d < FD; ++d) sd[d] += ci * u[o * FD + d];
    }
#pragma unroll
    for (int d = 0; d < FD; ++d)
        for (int off = 16; off; off >>= 1)
            sd[d] += __shfl_down_sync(0xffffffffu, sd[d], off);

    __shared__ float part[8][FD];
    __shared__ float fin[FD];
    __shared__ float fac;
    if (lane == 0)
#pragma unroll
        for (int d = 0; d < FD; ++d) part[wid][d] = sd[d];
    __syncthreads();
    if (t < FD) {
        float tot = 0.0f;
#pragma unroll
        for (int ww = 0; ww < 8; ++ww) tot += part[ww][t];
        fin[t] = tot;
    }
    __syncthreads();
    if (t == 0) {
        float l2 = 0.0f;
#pragma unroll
        for (int d = 0; d < FD; ++d) l2 += fin[d] * fin[d];
        fac = sqrtf(l2) / (1.0f + l2);
    }
    __syncthreads();
    if (t < FD) vout[((size_t)b * NCLS + o) * FD + t] = fin[t] * fac;
}

// =====================================================================
// heads
// =====================================================================
__global__ void head_kernel(const float* __restrict__ v,
                            const float* __restrict__ pred_w,
                            const float* __restrict__ pred_b,
                            const float* __restrict__ eos_w,
                            const float* __restrict__ eos_b,
                            float* __restrict__ out) {
    const int t = threadIdx.x;
    if (t >= BATCH * NCLS) return;
    const float* vv = v + (size_t)t * FD;
    float lg[NREL + 1];
#pragma unroll 4
    for (int r = 0; r < NREL; ++r) {
        float a = pred_b[r];
#pragma unroll
        for (int d = 0; d < FD; ++d) a += vv[d] * pred_w[r * FD + d];
        lg[r] = a;
    }
    {
        float a = eos_b[0];
#pragma unroll
        for (int d = 0; d < FD; ++d) a += vv[d] * eos_w[d];
        lg[NREL] = a;
    }
    float m = lg[0];
#pragma unroll
    for (int k = 1; k <= NREL; ++k) m = fmaxf(m, lg[k]);
    float s = 0.0f;
#pragma unroll
    for (int k = 0; k <= NREL; ++k) s += expf(lg[k] - m);
    const float ls = m + logf(s);
#pragma unroll
    for (int k = 0; k <= NREL; ++k) out[(size_t)t * (NREL + 1) + k] = lg[k] - ls;
}

// =====================================================================
extern "C" void kernel_launch(void* const* d_in, const int* in_sizes, int n_in,
                              void* d_out, int out_size) {
    const float* input   = (const float*)d_in[0];
    const float* conv1_w = (const float*)d_in[1];
    const float* conv1_b = (const float*)d_in[2];
    const float* prim_w  = (const float*)d_in[3];
    const float* prim_b  = (const float*)d_in[4];
    const float* caps_w  = (const float*)d_in[5];
    const float* b_route = (const float*)d_in[6];
    const float* pred_w  = (const float*)d_in[7];
    const float* pred_b  = (const float*)d_in[8];
    const float* eos_w   = (const float*)d_in[9];
    const float* eos_b   = (const float*)d_in[10];
    float* out = (float*)d_out;

    uint32_t *infp, *bf2p;
    uint4 *w1fp, *w2fp;
    float *prim4, *upp, *bbp, *vp;
    cudaGetSymbolAddress((void**)&infp, g_inf);
    cudaGetSymbolAddress((void**)&w1fp, g_w1f);
    cudaGetSymbolAddress((void**)&w2fp, g_w2f);
    cudaGetSymbolAddress((void**)&bf2p, g_bf2);
    cudaGetSymbolAddress((void**)&prim4, g_prim4);
    cudaGetSymbolAddress((void**)&upp, g_up);
    cudaGetSymbolAddress((void**)&bbp, g_bb);
    cudaGetSymbolAddress((void**)&vp, g_v);

    const int NBB = BATCH * NCAP * NCLS;
    const int NV = BATCH * NCLS * FD;
    const size_t NINF = (size_t)BATCH * IH * 10 * 1024;
    const int SMEM_C1 = 2 * 2560 * 16;     // 80KB

    cudaFuncSetAttribute(conv1_mma, cudaFuncAttributeMaxDynamicSharedMemorySize,
                         SMEM_C1);

    prep_inf<<<(unsigned)((NINF + 255) / 256), 256>>>(input, infp);
    prep_c1wf<<<(300 * 16 * 32 * 4 + 255) / 256, 256>>>(conv1_w,
                                                        (uint32_t*)w1fp);
    prep_c2wf<<<(NS2 * 16 * 32 * 4 + 255) / 256, 256>>>(prim_w,
                                                        (uint32_t*)w2fp);
    conv1_mma<<<dim3(2, OH1, BATCH), 256, SMEM_C1>>>(infp, w1fp, conv1_b,
                                                     (u16*)bf2p);
    conv2_mma<<<dim3(2, BATCH, KSPLIT), 256>>>(bf2p, w2fp, prim_b, prim4);
    squash_predict_kernel<<<dim3(NCAP, BATCH), 80>>>(prim4, caps_w, upp);
    route_s0_kernel<<<dim3(NCLS, BATCH), 256>>>(upp, b_route, vp);
    route_fused<<<dim3(NCLS, BATCH), 256>>>(upp, b_route, vp, vp + NV,
                                            bbp, bbp, 1);
    route_fused<<<dim3(NCLS, BATCH), 256>>>(upp, b_route, vp + NV, vp,
                                            bbp, bbp + NBB, 0);
    route_fused<<<dim3(NCLS, BATCH), 256>>>(upp, b_route, vp, vp + NV,
                                            bbp + NBB, bbp, 0);
    head_kernel<<<1, BATCH * NCLS>>>(vp + NV, pred_w, pred_b, eos_w, eos_b, out);
}

// round 14
// speedup vs baseline: 1.1095x; 1.0004x over previous
#include <cuda_runtime.h>
#include <cuda_fp16.h>
#include <math.h>
#include <stdint.h>

typedef unsigned short u16;

// ---------------- problem constants ----------------
#define BATCH 32
#define IH 120
#define IW 640
#define OH1 90            // only rows 0..89 consumed by conv2
#define NCAP 3456
#define NCLS 5
#define FD 16
#define JD 80
#define NREL 25
#define K1 4800
#define K2 25600
#define NPOS 108
#define KSPLIT 8
#define NS2 1600          // K2/16 k16-slices

// ---------------- device scratch ----------------
// conv1 B operand, fragment order: [(b*120+row)*10+slice][j 0..15][lane][2u32]
__device__ uint32_t g_inf[(size_t)BATCH * IH * 10 * 1024];
// conv1 A operand, fragment order: [step*16+rb][lane][4 u32]
__device__ uint4 g_w1f[300 * 16 * 32];
// conv2 A operand, fragment order: [s2*16+rb][lane][4 u32]
__device__ uint4 g_w2f[NS2 * 16 * 32];
// conv2 B operand (conv1 output), fragment order: [b][s2][nf 0..15][lane][2u32]
__device__ uint32_t g_bf2[(size_t)BATCH * NS2 * 16 * 64];
__device__ float g_prim4[KSPLIT][BATCH * 256 * NPOS];
__device__ float g_up[BATCH * NCAP * JD];
__device__ float g_bb[2][BATCH * NCAP * NCLS];
__device__ float g_v[2][BATCH * NCLS * FD];

// ---------------- helpers ----------------
__device__ __forceinline__ void mma16816(float* c, const uint32_t* a,
                                         const uint32_t* b) {
    asm volatile(
        "mma.sync.aligned.m16n8k16.row.col.f32.f16.f16.f32 "
        "{%0,%1,%2,%3}, {%4,%5,%6,%7}, {%8,%9}, {%0,%1,%2,%3};"
        : "+f"(c[0]), "+f"(c[1]), "+f"(c[2]), "+f"(c[3])
        : "r"(a[0]), "r"(a[1]), "r"(a[2]), "r"(a[3]), "r"(b[0]), "r"(b[1]));
}
__device__ __forceinline__ void cp16(uint32_t dst, const void* src) {
    asm volatile("cp.async.ca.shared.global [%0], [%1], 16;"
                 :: "r"(dst), "l"(src));
}
__device__ __forceinline__ void cp_commit() {
    asm volatile("cp.async.commit_group;");
}
__device__ __forceinline__ void cp_wait0() {
    asm volatile("cp.async.wait_group 0;");
}
__device__ __forceinline__ uint32_t pack2h(float v0, float v1) {
    __half2 h = __floats2half2_rn(v0, v1);
    return *(uint32_t*)&h;
}

// =====================================================================
// prep: input -> conv1 B fragment order.
// =====================================================================
__global__ void prep_inf(const float* __restrict__ in,
                         uint32_t* __restrict__ inf) {
    size_t idx = (size_t)blockIdx.x * 256 + threadIdx.x;
    if (idx >= (size_t)BATCH * IH * 10 * 1024) return;
    int w = idx & 1;
    int lane = (idx >> 1) & 31;
    int j = (idx >> 6) & 15;
    size_t t = idx >> 10;
    int sg = (int)(t % 10);
    size_t rowb = t / 10;
    int grp = lane >> 2, tig = lane & 3;
    int col0 = 4 * (8 * j + grp) + 16 * sg + 2 * tig + 8 * w;
    float v0 = (col0 < IW) ? in[rowb * IW + col0] : 0.0f;
    float v1 = (col0 + 1 < IW) ? in[rowb * IW + col0 + 1] : 0.0f;
    inf[idx] = pack2h(v0, v1);
}

// =====================================================================
// prep conv1 weights -> A fragment order.
// =====================================================================
__global__ void prep_c1wf(const float* __restrict__ w,
                          uint32_t* __restrict__ w1f) {
    int idx = blockIdx.x * 256 + threadIdx.x;   // 614400
    if (idx >= 300 * 16 * 32 * 4) return;
    int j = idx & 3;
    int lane = (idx >> 2) & 31;
    int rb = (idx >> 7) & 15;
    int step = idx >> 11;
    int grp = lane >> 2, tig = lane & 3;
    int c = rb * 16 + grp + (j & 1) * 8;
    int kk = 2 * tig + (j >> 1) * 8;
    int kh = step / 10, kws = step - 10 * kh;
    int kg = kh * 160 + kws * 16 + kk;
    w1f[idx] = pack2h(w[(size_t)c * K1 + kg], w[(size_t)c * K1 + kg + 1]);
}

// =====================================================================
// prep conv2 weights -> A fragment order [s2][rb][lane][j].
// k-order: k = r*256 + c1, r = kh*10+kw.
// =====================================================================
__global__ void prep_c2wf(const float* __restrict__ w2,
                          uint32_t* __restrict__ w2f) {
    int idx = blockIdx.x * 256 + threadIdx.x;   // 3,276,800
    if (idx >= NS2 * 16 * 32 * 4) return;
    int j = idx & 3;
    int lane = (idx >> 2) & 31;
    int rb = (idx >> 7) & 15;
    int s2 = idx >> 11;
    int grp = lane >> 2, tig = lane & 3;
    int c2 = rb * 16 + grp + (j & 1) * 8;
    int k0 = s2 * 16 + 2 * tig + (j >> 1) * 8;
    float v0 = w2[((size_t)c2 * 256 + (k0 & 255)) * 100 + (k0 >> 8)];
    float v1 = w2[((size_t)c2 * 256 + ((k0 + 1) & 255)) * 100 + ((k0 + 1) >> 8)];
    w2f[idx] = pack2h(v0, v1);
}

// =====================================================================
// conv1 via HMMA, pure fp16, fragment-order operands (R11 structure).
// CTA = (mt, oh, b): M128 x N128(ow) x K4800. 8 warps 2(M)x4(N),
// warp 64x32, 2 CTAs/SM. A: full kh-row per cp.async stage (80KB dyn
// smem, 30 syncs). B: direct LDG.64.
// Epilogue: bias+relu -> fp16 written DIRECTLY in conv2-B-fragment order.
// =====================================================================
__global__ __launch_bounds__(256, 2)
void conv1_mma(const uint32_t* __restrict__ inf, const uint4* __restrict__ w1f,
               const float* __restrict__ bias, u16* __restrict__ bf2) {
    extern __shared__ uint4 sA[];   // [2][2560]

    const int tid = threadIdx.x;
    const int wid = tid >> 5, lane = tid & 31;
    const int grp = lane >> 2, tig = lane & 3;
    const int wm = wid >> 2, wn = wid & 3;
    const int mt = blockIdx.x, oh = blockIdx.y, b = blockIdx.z;

    float acc[4][4][4] = {};

    const uint32_t sA0 = (uint32_t)__cvta_generic_to_shared(&sA[0]);

    auto stageA = [&](int it, int stg) {
#pragma unroll
        for (int r = 0; r < 10; ++r) {
            const int c = tid + (r << 8);
            const int slice = c >> 8;
            const int rbl = (c >> 5) & 7;
            const int ln = c & 31;
            const int step = it * 10 + slice;
            cp16(sA0 + (stg * 2560 + c) * 16,
                 w1f + ((step * 16 + mt * 8 + rbl) * 32 + ln));
        }
        cp_commit();
    };

    stageA(0, 0);
    cp_wait0();
    __syncthreads();

    for (int it = 0; it < 30; ++it) {                  // it = kh
        const int stg = it & 1;
        if (it < 29) stageA(it + 1, stg ^ 1);

        const size_t rowb = (size_t)b * IH + oh + it;
        const uint32_t* bb = inf + rowb * 10240 + wn * 256 + lane * 2;
#pragma unroll
        for (int s = 0; s < 10; ++s) {
            uint2 bf[4];
#pragma unroll
            for (int nf = 0; nf < 4; ++nf)
                bf[nf] = *(const uint2*)(bb + s * 1024 + nf * 64);
            uint4 af[4];
#pragma unroll
            for (int mf = 0; mf < 4; ++mf)
                af[mf] = sA[stg * 2560 + s * 256 + (wm * 4 + mf) * 32 + lane];
#pragma unroll
            for (int mf = 0; mf < 4; ++mf)
#pragma unroll
                for (int nf = 0; nf < 4; ++nf)
                    mma16816(acc[mf][nf], (const uint32_t*)&af[mf],
                             (const uint32_t*)&bf[nf]);
        }
        cp_wait0();
        __syncthreads();
    }

    // epilogue: bias + relu -> fp16, conv2-B-fragment order.
    // element: c = mt*128+wm*64+mf*16+grp+(i>>1)*8, ow = wn*32+nf*8+2tig+(i&1)
    // k = r*256+c -> s2 = r*16 + mt*8+wm*4+mf, kk = grp+8*(i>>1)
    // B-frag: lane2 = (pos&7)*4 + (grp>>1), word = i>>1, half = grp&1
    const int ohh = oh / 10, kh2 = oh - 10 * ohh;
#pragma unroll
    for (int mf = 0; mf < 4; ++mf) {
#pragma unroll
        for (int nf = 0; nf < 4; ++nf) {
#pragma unroll
            for (int i = 0; i < 4; ++i) {
                const int c = mt * 128 + wm * 64 + mf * 16 + grp + (i >> 1) * 8;
                const int ow = wn * 32 + nf * 8 + 2 * tig + (i & 1);
                if (ow < 120) {
                    float v = fmaxf(acc[mf][nf][i] + bias[c], 0.0f);
                    const int pos = ohh * 12 + ow / 10;
                    const int r = kh2 * 10 + (ow % 10);
                    const int s2 = r * 16 + mt * 8 + wm * 4 + mf;
                    const int lane2 = (pos & 7) * 4 + (grp >> 1);
                    const size_t o =
                        ((((size_t)b * NS2 + s2) * 16 + (pos >> 3)) * 32 +
                         lane2) * 4 + (i >> 1) * 2 + (grp & 1);
                    bf2[o] = __half_as_ushort(__float2half_rn(v));
                }
            }
        }
    }
}

// =====================================================================
// conv2 via HMMA, barrier-free fragment-order: M=256(mt 2) x N=128(pad)
// x K=25600, 8-way K split. grid (2, 32, 8). Warp 64x32, 2 CTAs/SM.
// n >= 108 columns are garbage (never written) and discarded at store.
// =====================================================================
__global__ __launch_bounds__(256, 2)
void conv2_mma(const uint32_t* __restrict__ bf2, const uint4* __restrict__ w2f,
               const float* __restrict__ pb, float* __restrict__ prim4) {
    const int tid = threadIdx.x;
    const int wid = tid >> 5, lane = tid & 31;
    const int grp = lane >> 2, tig = lane & 3;
    const int wm = wid >> 2, wn = wid & 3;
    const int mt = blockIdx.x, b = blockIdx.y, ks = blockIdx.z;

    float acc[4][4][4] = {};

    const int NSL = NS2 / KSPLIT;   // 200 slices per split
    const uint4* Ab = w2f + ((size_t)(ks * NSL) * 16 + mt * 8 + wm * 4) * 32 +
                      lane;
    const uint32_t* Bb = bf2 + (((size_t)b * NS2 + ks * NSL) * 16 + wn * 4) *
                         64 + lane * 2;

    for (int s = 0; s < NSL; ++s) {
        uint2 bfr[4];
#pragma unroll
        for (int nf = 0; nf < 4; ++nf)
            bfr[nf] = *(const uint2*)(Bb + (size_t)s * 1024 + nf * 64);
        uint4 af[4];
#pragma unroll
        for (int mf = 0; mf < 4; ++mf)
            af[mf] = Ab[((size_t)s * 16 + mf) * 32];
#pragma unroll
        for (int mf = 0; mf < 4; ++mf)
#pragma unroll
            for (int nf = 0; nf < 4; ++nf)
                mma16816(acc[mf][nf], (const uint32_t*)&af[mf],
                         (const uint32_t*)&bfr[nf]);
    }

    float* outp = prim4 + (size_t)ks * (BATCH * 256 * NPOS);
#pragma unroll
    for (int mf = 0; mf < 4; ++mf) {
#pragma unroll
        for (int nf = 0; nf < 4; ++nf) {
#pragma unroll
            for (int i = 0; i < 4; ++i) {
                const int c2 = mt * 128 + wm * 64 + mf * 16 + grp + (i >> 1) * 8;
                const int n = (wn * 4 + nf) * 8 + 2 * tig + (i & 1);
                if (n < NPOS) {
                    float v = acc[mf][nf][i] + (ks == 0 ? pb[c2] : 0.0f);
                    outp[((size_t)b * 256 + c2) * NPOS + n] = v;
                }
            }
        }
    }
}

// =====================================================================
// squash + caps prediction (sums KSPLIT conv2 partials)
// =====================================================================
__global__ void squash_predict_kernel(const float* __restrict__ prim4,
                                      const float* __restrict__ caps_w,
                                      float* __restrict__ up) {
    __shared__ float su[8];
    __shared__ float sfac;
    const int i = blockIdx.x;
    const int b = blockIdx.y;
    const int g = i / NPOS;
    const int p = i - g * NPOS;
    const int t = threadIdx.x;
    const int SL = BATCH * 256 * NPOS;

    if (t < 8) {
        size_t o = ((size_t)b * 256 + g * 8 + t) * NPOS + p;
        float acc = 0.0f;
#pragma unroll
        for (int q = 0; q < KSPLIT; ++q) acc += prim4[o + (size_t)q * SL];
        su[t] = acc;
    }
    __syncthreads();
    if (t == 0) {
        float l2 = 0.0f;
#pragma unroll
        for (int d = 0; d < 8; ++d) l2 += su[d] * su[d];
        sfac = sqrtf(l2) / (1.0f + l2);
    }
    __syncthreads();
    const float f = sfac;
    const float* cw = caps_w + (size_t)i * 8 * JD + t;
    float a = 0.0f;
#pragma unroll
    for (int d = 0; d < 8; ++d) a += su[d] * f * cw[d * JD];
    up[((size_t)b * NCAP + i) * JD + t] = a;
}

// =====================================================================
// routing iteration 0
// =====================================================================
__global__ void route_s0_kernel(const float* __restrict__ up,
                                const float* __restrict__ b_route,
                                float* __restrict__ vout) {
    const int o = blockIdx.x;
    const int b = blockIdx.y;
    const int t = threadIdx.x;
    const int lane = t & 31, wid = t >> 5;

    float sd[FD];
#pragma unroll
    for (int d = 0; d < FD; ++d) sd[d] = 0.0f;

    for (int i = t; i < NCAP; i += 256) {
        float br[NCLS];
#pragma unroll
        for (int oo = 0; oo < NCLS; ++oo) br[oo] = b_route[i * NCLS + oo];
        float m = br[0];
#pragma unroll
        for (int oo = 1; oo < NCLS; ++oo) m = fmaxf(m, br[oo]);
        float s = 0.0f;
#pragma unroll
        for (int oo = 0; oo < NCLS; ++oo) s += expf(br[oo] - m);
        float ci = expf(br[o] - m) / s;
        const float* u = up + ((size_t)b * NCAP + i) * JD + o * FD;
#pragma unroll
        for (int d = 0; d < FD; ++d) sd[d] += ci * u[d];
    }
#pragma unroll
    for (int d = 0; d < FD; ++d)
        for (int off = 16; off; off >>= 1)
            sd[d] += __shfl_down_sync(0xffffffffu, sd[d], off);

    __shared__ float part[8][FD];
    __shared__ float fin[FD];
    __shared__ float fac;
    if (lane == 0)
#pragma unroll
        for (int d = 0; d < FD; ++d) part[wid][d] = sd[d];
    __syncthreads();
    if (t < FD) {
        float tot = 0.0f;
#pragma unroll
        for (int ww = 0; ww < 8; ++ww) tot += part[ww][t];
        fin[t] = tot;
    }
    __syncthreads();
    if (t == 0) {
        float l2 = 0.0f;
#pragma unroll
        for (int d = 0; d < FD; ++d) l2 += fin[d] * fin[d];
        fac = sqrtf(l2) / (1.0f + l2);
    }
    __syncthreads();
    if (t < FD) vout[((size_t)b * NCLS + o) * FD + t] = fin[t] * fac;
}

// =====================================================================
// fused routing iteration (double-buffered bb and v)
// =====================================================================
__global__ void route_fused(const float* __restrict__ up,
                            const float* __restrict__ b_route,
                            const float* __restrict__ vin,
                            float* __restrict__ vout,
                            const float* __restrict__ bb_rd,
                            float* __restrict__ bb_wr, int first) {
    const int o = blockIdx.x;
    const int b = blockIdx.y;
    const int t = threadIdx.x;
    const int lane = t & 31, wid = t >> 5;

    __shared__ float sv[JD];
    if (t < JD) sv[t] = vin[b * JD + t];
    __syncthreads();

    float sd[FD];
#pragma unroll
    for (int d = 0; d < FD; ++d) sd[d] = 0.0f;

    for (int i = t; i < NCAP; i += 256) {
        const size_t base = ((size_t)b * NCAP + i);
        float u[JD];
        const float4* u4 = (const float4*)(up + base * JD);
#pragma unroll
        for (int q = 0; q < JD / 4; ++q) {
            float4 vv = u4[q];
            u[4 * q] = vv.x; u[4 * q + 1] = vv.y;
            u[4 * q + 2] = vv.z; u[4 * q + 3] = vv.w;
        }
        float nb[NCLS];
#pragma unroll
        for (int oo = 0; oo < NCLS; ++oo) {
            float dot = 0.0f;
#pragma unroll
            for (int d = 0; d < FD; ++d) dot += u[oo * FD + d] * sv[oo * FD + d];
            float prev = first ? b_route[i * NCLS + oo] : bb_rd[base * NCLS + oo];
            nb[oo] = prev + dot;
        }
        if (o == 0) {
#pragma unroll
            for (int oo = 0; oo < NCLS; ++oo) bb_wr[base * NCLS + oo] = nb[oo];
        }
        float m = nb[0];
#pragma unroll
        for (int oo = 1; oo < NCLS; ++oo) m = fmaxf(m, nb[oo]);
        float s = 0.0f;
#pragma unroll
        for (int oo = 0; oo < NCLS; ++oo) s += expf(nb[oo] - m);
        float ci = expf(nb[o] - m) / s;
#pragma unroll
        for (int d = 0; d < FD; ++d) sd[d] += ci * u[o * FD + d];
    }
#pragma unroll
    for (int d = 0; d < FD; ++d)
        for (int off = 16; off; off >>= 1)
            sd[d] += __shfl_down_sync(0xffffffffu, sd[d], off);

    __shared__ float part[8][FD];
    __shared__ float fin[FD];
    __shared__ float fac;
    if (lane == 0)
#pragma unroll
        for (int d = 0; d < FD; ++d) part[wid][d] = sd[d];
    __syncthreads();
    if (t < FD) {
        float tot = 0.0f;
#pragma unroll
        for (int ww = 0; ww < 8; ++ww) tot += part[ww][t];
        fin[t] = tot;
    }
    __syncthreads();
    if (t == 0) {
        float l2 = 0.0f;
#pragma unroll
        for (int d = 0; d < FD; ++d) l2 += fin[d] * fin[d];
        fac = sqrtf(l2) / (1.0f + l2);
    }
    __syncthreads();
    if (t < FD) vout[((size_t)b * NCLS + o) * FD + t] = fin[t] * fac;
}

// =====================================================================
// heads
// =====================================================================
__global__ void head_kernel(const float* __restrict__ v,
                            const float* __restrict__ pred_w,
                            const float* __restrict__ pred_b,
                            const float* __restrict__ eos_w,
                            const float* __restrict__ eos_b,
                            float* __restrict__ out) {
    const int t = threadIdx.x;
    if (t >= BATCH * NCLS) return;
    const float* vv = v + (size_t)t * FD;
    float lg[NREL + 1];
#pragma unroll 4
    for (int r = 0; r < NREL; ++r) {
        float a = pred_b[r];
#pragma unroll
        for (int d = 0; d < FD; ++d) a += vv[d] * pred_w[r * FD + d];
        lg[r] = a;
    }
    {
        float a = eos_b[0];
#pragma unroll
        for (int d = 0; d < FD; ++d) a += vv[d] * eos_w[d];
        lg[NREL] = a;
    }
    float m = lg[0];
#pragma unroll
    for (int k = 1; k <= NREL; ++k) m = fmaxf(m, lg[k]);
    float s = 0.0f;
#pragma unroll
    for (int k = 0; k <= NREL; ++k) s += expf(lg[k] - m);
    const float ls = m + logf(s);
#pragma unroll
    for (int k = 0; k <= NREL; ++k) out[(size_t)t * (NREL + 1) + k] = lg[k] - ls;
}

// =====================================================================
extern "C" void kernel_launch(void* const* d_in, const int* in_sizes, int n_in,
                              void* d_out, int out_size) {
    const float* input   = (const float*)d_in[0];
    const float* conv1_w = (const float*)d_in[1];
    const float* conv1_b = (const float*)d_in[2];
    const float* prim_w  = (const float*)d_in[3];
    const float* prim_b  = (const float*)d_in[4];
    const float* caps_w  = (const float*)d_in[5];
    const float* b_route = (const float*)d_in[6];
    const float* pred_w  = (const float*)d_in[7];
    const float* pred_b  = (const float*)d_in[8];
    const float* eos_w   = (const float*)d_in[9];
    const float* eos_b   = (const float*)d_in[10];
    float* out = (float*)d_out;

    uint32_t *infp, *bf2p;
    uint4 *w1fp, *w2fp;
    float *prim4, *upp, *bbp, *vp;
    cudaGetSymbolAddress((void**)&infp, g_inf);
    cudaGetSymbolAddress((void**)&w1fp, g_w1f);
    cudaGetSymbolAddress((void**)&w2fp, g_w2f);
    cudaGetSymbolAddress((void**)&bf2p, g_bf2);
    cudaGetSymbolAddress((void**)&prim4, g_prim4);
    cudaGetSymbolAddress((void**)&upp, g_up);
    cudaGetSymbolAddress((void**)&bbp, g_bb);
    cudaGetSymbolAddress((void**)&vp, g_v);

    const int NBB = BATCH * NCAP * NCLS;
    const int NV = BATCH * NCLS * FD;
    const size_t NINF = (size_t)BATCH * IH * 10 * 1024;
    const int SMEM_C1 = 2 * 2560 * 16;     // 80KB

    cudaFuncSetAttribute(conv1_mma, cudaFuncAttributeMaxDynamicSharedMemorySize,
                         SMEM_C1);

    prep_inf<<<(unsigned)((NINF + 255) / 256), 256>>>(input, infp);
    prep_c1wf<<<(300 * 16 * 32 * 4 + 255) / 256, 256>>>(conv1_w,
                                                        (uint32_t*)w1fp);
    prep_c2wf<<<(NS2 * 16 * 32 * 4 + 255) / 256, 256>>>(prim_w,
                                                        (uint32_t*)w2fp);
    conv1_mma<<<dim3(2, OH1, BATCH), 256, SMEM_C1>>>(infp, w1fp, conv1_b,
                                                     (u16*)bf2p);
    conv2_mma<<<dim3(2, BATCH, KSPLIT), 256>>>(bf2p, w2fp, prim_b, prim4);
    squash_predict_kernel<<<dim3(NCAP, BATCH), 80>>>(prim4, caps_w, upp);
    route_s0_kernel<<<dim3(NCLS, BATCH), 256>>>(upp, b_route, vp);
    route_fused<<<dim3(NCLS, BATCH), 256>>>(upp, b_route, vp, vp + NV,
                                            bbp, bbp, 1);
    route_fused<<<dim3(NCLS, BATCH), 256>>>(upp, b_route, vp + NV, vp,
                                            bbp, bbp + NBB, 0);
    route_fused<<<dim3(NCLS, BATCH), 256>>>(upp, b_route, vp, vp + NV,
                                            bbp + NBB, bbp, 0);
    head_kernel<<<1, BATCH * NCLS>>>(vp + NV, pred_w, pred_b, eos_w, eos_b, out);
}

// round 15
// speedup vs baseline: 1.1896x; 1.0722x over previous
#include <cuda_runtime.h>
#include <cuda_fp16.h>
#include <math.h>
#include <stdint.h>

typedef unsigned short u16;

// ---------------- problem constants ----------------
#define BATCH 32
#define IH 120
#define IW 640
#define OH1 90            // only rows 0..89 consumed by conv2
#define NCAP 3456
#define NCLS 5
#define FD 16
#define JD 80
#define NREL 25
#define K1 4800
#define K2 25600
#define NPOS 108
#define KSPLIT 8
#define NS2 1600          // K2/16 k16-slices

// ---------------- device scratch ----------------
// conv1 B operand, fragment order: [(b*120+row)*10+slice][j 0..15][lane][2u32]
__device__ uint32_t g_inf[(size_t)BATCH * IH * 10 * 1024];
// conv1 A operand, fragment order: [step*16+rb][lane][4 u32]
__device__ uint4 g_w1f[300 * 16 * 32];
// conv2 A operand, fragment order: [s2*16+rb][lane][4 u32]
__device__ uint4 g_w2f[NS2 * 16 * 32];
// conv2 B operand (conv1 output), fragment order: [b][s2][nf 0..15][lane][2u32]
__device__ uint32_t g_bf2[(size_t)BATCH * NS2 * 16 * 64];
__device__ float g_prim4[KSPLIT][BATCH * 256 * NPOS];
__device__ float g_up[BATCH * NCAP * JD];

// ---------------- helpers ----------------
__device__ __forceinline__ void mma16816(float* c, const uint32_t* a,
                                         const uint32_t* b) {
    asm volatile(
        "mma.sync.aligned.m16n8k16.row.col.f32.f16.f16.f32 "
        "{%0,%1,%2,%3}, {%4,%5,%6,%7}, {%8,%9}, {%0,%1,%2,%3};"
        : "+f"(c[0]), "+f"(c[1]), "+f"(c[2]), "+f"(c[3])
        : "r"(a[0]), "r"(a[1]), "r"(a[2]), "r"(a[3]), "r"(b[0]), "r"(b[1]));
}
__device__ __forceinline__ void cp16(uint32_t dst, const void* src) {
    asm volatile("cp.async.ca.shared.global [%0], [%1], 16;"
                 :: "r"(dst), "l"(src));
}
__device__ __forceinline__ void cp_commit() {
    asm volatile("cp.async.commit_group;");
}
__device__ __forceinline__ void cp_wait0() {
    asm volatile("cp.async.wait_group 0;");
}
__device__ __forceinline__ uint32_t pack2h(float v0, float v1) {
    __half2 h = __floats2half2_rn(v0, v1);
    return *(uint32_t*)&h;
}

// =====================================================================
// prep: input -> conv1 B fragment order.
// =====================================================================
__global__ void prep_inf(const float* __restrict__ in,
                         uint32_t* __restrict__ inf) {
    size_t idx = (size_t)blockIdx.x * 256 + threadIdx.x;
    if (idx >= (size_t)BATCH * IH * 10 * 1024) return;
    int w = idx & 1;
    int lane = (idx >> 1) & 31;
    int j = (idx >> 6) & 15;
    size_t t = idx >> 10;
    int sg = (int)(t % 10);
    size_t rowb = t / 10;
    int grp = lane >> 2, tig = lane & 3;
    int col0 = 4 * (8 * j + grp) + 16 * sg + 2 * tig + 8 * w;
    float v0 = (col0 < IW) ? in[rowb * IW + col0] : 0.0f;
    float v1 = (col0 + 1 < IW) ? in[rowb * IW + col0 + 1] : 0.0f;
    inf[idx] = pack2h(v0, v1);
}

// =====================================================================
// prep conv1 weights -> A fragment order.
// =====================================================================
__global__ void prep_c1wf(const float* __restrict__ w,
                          uint32_t* __restrict__ w1f) {
    int idx = blockIdx.x * 256 + threadIdx.x;   // 614400
    if (idx >= 300 * 16 * 32 * 4) return;
    int j = idx & 3;
    int lane = (idx >> 2) & 31;
    int rb = (idx >> 7) & 15;
    int step = idx >> 11;
    int grp = lane >> 2, tig = lane & 3;
    int c = rb * 16 + grp + (j & 1) * 8;
    int kk = 2 * tig + (j >> 1) * 8;
    int kh = step / 10, kws = step - 10 * kh;
    int kg = kh * 160 + kws * 16 + kk;
    w1f[idx] = pack2h(w[(size_t)c * K1 + kg], w[(size_t)c * K1 + kg + 1]);
}

// =====================================================================
// prep conv2 weights -> A fragment order [s2][rb][lane][j].
// =====================================================================
__global__ void prep_c2wf(const float* __restrict__ w2,
                          uint32_t* __restrict__ w2f) {
    int idx = blockIdx.x * 256 + threadIdx.x;   // 3,276,800
    if (idx >= NS2 * 16 * 32 * 4) return;
    int j = idx & 3;
    int lane = (idx >> 2) & 31;
    int rb = (idx >> 7) & 15;
    int s2 = idx >> 11;
    int grp = lane >> 2, tig = lane & 3;
    int c2 = rb * 16 + grp + (j & 1) * 8;
    int k0 = s2 * 16 + 2 * tig + (j >> 1) * 8;
    float v0 = w2[((size_t)c2 * 256 + (k0 & 255)) * 100 + (k0 >> 8)];
    float v1 = w2[((size_t)c2 * 256 + ((k0 + 1) & 255)) * 100 + ((k0 + 1) >> 8)];
    w2f[idx] = pack2h(v0, v1);
}

// =====================================================================
// conv1 via HMMA (R11/R14 structure, unchanged — local optimum).
// =====================================================================
__global__ __launch_bounds__(256, 2)
void conv1_mma(const uint32_t* __restrict__ inf, const uint4* __restrict__ w1f,
               const float* __restrict__ bias, u16* __restrict__ bf2) {
    extern __shared__ uint4 sA[];   // [2][2560]

    const int tid = threadIdx.x;
    const int wid = tid >> 5, lane = tid & 31;
    const int grp = lane >> 2, tig = lane & 3;
    const int wm = wid >> 2, wn = wid & 3;
    const int mt = blockIdx.x, oh = blockIdx.y, b = blockIdx.z;

    float acc[4][4][4] = {};

    const uint32_t sA0 = (uint32_t)__cvta_generic_to_shared(&sA[0]);

    auto stageA = [&](int it, int stg) {
#pragma unroll
        for (int r = 0; r < 10; ++r) {
            const int c = tid + (r << 8);
            const int slice = c >> 8;
            const int rbl = (c >> 5) & 7;
            const int ln = c & 31;
            const int step = it * 10 + slice;
            cp16(sA0 + (stg * 2560 + c) * 16,
                 w1f + ((step * 16 + mt * 8 + rbl) * 32 + ln));
        }
        cp_commit();
    };

    stageA(0, 0);
    cp_wait0();
    __syncthreads();

    for (int it = 0; it < 30; ++it) {                  // it = kh
        const int stg = it & 1;
        if (it < 29) stageA(it + 1, stg ^ 1);

        const size_t rowb = (size_t)b * IH + oh + it;
        const uint32_t* bb = inf + rowb * 10240 + wn * 256 + lane * 2;
#pragma unroll
        for (int s = 0; s < 10; ++s) {
            uint2 bf[4];
#pragma unroll
            for (int nf = 0; nf < 4; ++nf)
                bf[nf] = *(const uint2*)(bb + s * 1024 + nf * 64);
            uint4 af[4];
#pragma unroll
            for (int mf = 0; mf < 4; ++mf)
                af[mf] = sA[stg * 2560 + s * 256 + (wm * 4 + mf) * 32 + lane];
#pragma unroll
            for (int mf = 0; mf < 4; ++mf)
#pragma unroll
                for (int nf = 0; nf < 4; ++nf)
                    mma16816(acc[mf][nf], (const uint32_t*)&af[mf],
                             (const uint32_t*)&bf[nf]);
        }
        cp_wait0();
        __syncthreads();
    }

    // epilogue: bias + relu -> fp16, conv2-B-fragment order.
    const int ohh = oh / 10, kh2 = oh - 10 * ohh;
#pragma unroll
    for (int mf = 0; mf < 4; ++mf) {
#pragma unroll
        for (int nf = 0; nf < 4; ++nf) {
#pragma unroll
            for (int i = 0; i < 4; ++i) {
                const int c = mt * 128 + wm * 64 + mf * 16 + grp + (i >> 1) * 8;
                const int ow = wn * 32 + nf * 8 + 2 * tig + (i & 1);
                if (ow < 120) {
                    float v = fmaxf(acc[mf][nf][i] + bias[c], 0.0f);
                    const int pos = ohh * 12 + ow / 10;
                    const int r = kh2 * 10 + (ow % 10);
                    const int s2 = r * 16 + mt * 8 + wm * 4 + mf;
                    const int lane2 = (pos & 7) * 4 + (grp >> 1);
                    const size_t o =
                        ((((size_t)b * NS2 + s2) * 16 + (pos >> 3)) * 32 +
                         lane2) * 4 + (i >> 1) * 2 + (grp & 1);
                    bf2[o] = __half_as_ushort(__float2half_rn(v));
                }
            }
        }
    }
}

// =====================================================================
// conv2 via HMMA, barrier-free fragment-order (R14 structure, unchanged).
// =====================================================================
__global__ __launch_bounds__(256, 2)
void conv2_mma(const uint32_t* __restrict__ bf2, const uint4* __restrict__ w2f,
               const float* __restrict__ pb, float* __restrict__ prim4) {
    const int tid = threadIdx.x;
    const int wid = tid >> 5, lane = tid & 31;
    const int grp = lane >> 2, tig = lane & 3;
    const int wm = wid >> 2, wn = wid & 3;
    const int mt = blockIdx.x, b = blockIdx.y, ks = blockIdx.z;

    float acc[4][4][4] = {};

    const int NSL = NS2 / KSPLIT;   // 200
    const uint4* Ab = w2f + ((size_t)(ks * NSL) * 16 + mt * 8 + wm * 4) * 32 +
                      lane;
    const uint32_t* Bb = bf2 + (((size_t)b * NS2 + ks * NSL) * 16 + wn * 4) *
                         64 + lane * 2;

    for (int s = 0; s < NSL; ++s) {
        uint2 bfr[4];
#pragma unroll
        for (int nf = 0; nf < 4; ++nf)
            bfr[nf] = *(const uint2*)(Bb + (size_t)s * 1024 + nf * 64);
        uint4 af[4];
#pragma unroll
        for (int mf = 0; mf < 4; ++mf)
            af[mf] = Ab[((size_t)s * 16 + mf) * 32];
#pragma unroll
        for (int mf = 0; mf < 4; ++mf)
#pragma unroll
            for (int nf = 0; nf < 4; ++nf)
                mma16816(acc[mf][nf], (const uint32_t*)&af[mf],
                         (const uint32_t*)&bfr[nf]);
    }

    float* outp = prim4 + (size_t)ks * (BATCH * 256 * NPOS);
#pragma unroll
    for (int mf = 0; mf < 4; ++mf) {
#pragma unroll
        for (int nf = 0; nf < 4; ++nf) {
#pragma unroll
            for (int i = 0; i < 4; ++i) {
                const int c2 = mt * 128 + wm * 64 + mf * 16 + grp + (i >> 1) * 8;
                const int n = (wn * 4 + nf) * 8 + 2 * tig + (i & 1);
                if (n < NPOS) {
                    float v = acc[mf][nf][i] + (ks == 0 ? pb[c2] : 0.0f);
                    outp[((size_t)b * 256 + c2) * NPOS + n] = v;
                }
            }
        }
    }
}

// =====================================================================
// squash + caps prediction (sums KSPLIT conv2 partials)
// =====================================================================
__global__ void squash_predict_kernel(const float* __restrict__ prim4,
                                      const float* __restrict__ caps_w,
                                      float* __restrict__ up) {
    __shared__ float su[8];
    __shared__ float sfac;
    const int i = blockIdx.x;
    const int b = blockIdx.y;
    const int g = i / NPOS;
    const int p = i - g * NPOS;
    const int t = threadIdx.x;
    const int SL = BATCH * 256 * NPOS;

    if (t < 8) {
        size_t o = ((size_t)b * 256 + g * 8 + t) * NPOS + p;
        float acc = 0.0f;
#pragma unroll
        for (int q = 0; q < KSPLIT; ++q) acc += prim4[o + (size_t)q * SL];
        su[t] = acc;
    }
    __syncthreads();
    if (t == 0) {
        float l2 = 0.0f;
#pragma unroll
        for (int d = 0; d < 8; ++d) l2 += su[d] * su[d];
        sfac = sqrtf(l2) / (1.0f + l2);
    }
    __syncthreads();
    const float f = sfac;
    const float* cw = caps_w + (size_t)i * 8 * JD + t;
    float a = 0.0f;
#pragma unroll
    for (int d = 0; d < 8; ++d) a += su[d] * f * cw[d * JD];
    up[((size_t)b * NCAP + i) * JD + t] = a;
}

// =====================================================================
// FUSED routing (all 4 iterations) + heads. One CTA per batch element.
// bb state lives entirely in smem (69KB); v ping-pongs in smem.
// dyn smem: bb[NCAP*5] + fin[80] + fac[5] + part[8*80] + v[80]
// =====================================================================
#define RSM_BB 0
#define RSM_FIN (NCAP * NCLS)
#define RSM_FAC (RSM_FIN + 80)
#define RSM_PART (RSM_FAC + 8)
#define RSM_V (RSM_PART + 8 * 80)
#define RSM_TOT (RSM_V + 80)

__global__ __launch_bounds__(256, 1)
void route_all(const float* __restrict__ up, const float* __restrict__ b_route,
               const float* __restrict__ pred_w,
               const float* __restrict__ pred_b,
               const float* __restrict__ eos_w,
               const float* __restrict__ eos_b, float* __restrict__ out) {
    extern __shared__ float rs[];
    float* s_bb = rs + RSM_BB;
    float* s_fin = rs + RSM_FIN;
    float* s_fac = rs + RSM_FAC;
    float* s_part = rs + RSM_PART;
    float* s_v = rs + RSM_V;

    const int b = blockIdx.x;
    const int t = threadIdx.x;
    const int lane = t & 31, wid = t >> 5;
    const float* upb = up + (size_t)b * NCAP * JD;

    // block-reduce helper inlined 4x via macro-style lambda
    auto reduce_squash = [&](float sd[NCLS][FD]) {
#pragma unroll
        for (int o = 0; o < NCLS; ++o)
#pragma unroll
            for (int d = 0; d < FD; ++d)
#pragma unroll
                for (int off = 16; off; off >>= 1)
                    sd[o][d] += __shfl_down_sync(0xffffffffu, sd[o][d], off);
        if (lane == 0)
#pragma unroll
            for (int o = 0; o < NCLS; ++o)
#pragma unroll
                for (int d = 0; d < FD; ++d)
                    s_part[wid * 80 + o * FD + d] = sd[o][d];
        __syncthreads();
        if (t < 80) {
            float tot = 0.0f;
#pragma unroll
            for (int w = 0; w < 8; ++w) tot += s_part[w * 80 + t];
            s_fin[t] = tot;
        }
        __syncthreads();
        if (t < NCLS) {
            float l2 = 0.0f;
#pragma unroll
            for (int d = 0; d < FD; ++d) {
                float x = s_fin[t * FD + d];
                l2 += x * x;
            }
            s_fac[t] = sqrtf(l2) / (1.0f + l2);
        }
        __syncthreads();
        if (t < 80) s_v[t] = s_fin[t] * s_fac[t / FD];
        __syncthreads();
    };

    // ---- iteration 0: c = softmax(b_route), s = sum c*u, v = squash ----
    {
        float sd[NCLS][FD] = {};
        for (int i = t; i < NCAP; i += 256) {
            float br[NCLS];
#pragma unroll
            for (int o = 0; o < NCLS; ++o) br[o] = b_route[i * NCLS + o];
            float m = br[0];
#pragma unroll
            for (int o = 1; o < NCLS; ++o) m = fmaxf(m, br[o]);
            float ssum = 0.0f;
            float ce[NCLS];
#pragma unroll
            for (int o = 0; o < NCLS; ++o) {
                ce[o] = expf(br[o] - m);
                ssum += ce[o];
            }
            const float inv = 1.0f / ssum;
            const float4* u4 = (const float4*)(upb + (size_t)i * JD);
#pragma unroll
            for (int o = 0; o < NCLS; ++o) {
                const float ci = ce[o] * inv;
#pragma unroll
                for (int q = 0; q < 4; ++q) {
                    float4 uv = u4[o * 4 + q];
                    sd[o][4 * q] += ci * uv.x;
                    sd[o][4 * q + 1] += ci * uv.y;
                    sd[o][4 * q + 2] += ci * uv.z;
                    sd[o][4 * q + 3] += ci * uv.w;
                }
            }
        }
        reduce_squash(sd);
    }

    // ---- 3 routing iterations (bb in smem) ----
    for (int it = 0; it < 3; ++it) {
        float sd[NCLS][FD] = {};
        for (int i = t; i < NCAP; i += 256) {
            const float4* u4 = (const float4*)(upb + (size_t)i * JD);
            float nb[NCLS];
#pragma unroll
            for (int o = 0; o < NCLS; ++o) {
                float dot = 0.0f;
#pragma unroll
                for (int q = 0; q < 4; ++q) {
                    float4 uv = u4[o * 4 + q];
                    dot += uv.x * s_v[o * FD + 4 * q] +
                           uv.y * s_v[o * FD + 4 * q + 1] +
                           uv.z * s_v[o * FD + 4 * q + 2] +
                           uv.w * s_v[o * FD + 4 * q + 3];
                }
                float prev = (it == 0) ? b_route[i * NCLS + o]
                                       : s_bb[i * NCLS + o];
                nb[o] = prev + dot;
                s_bb[i * NCLS + o] = nb[o];
            }
            float m = nb[0];
#pragma unroll
            for (int o = 1; o < NCLS; ++o) m = fmaxf(m, nb[o]);
            float ssum = 0.0f;
#pragma unroll
            for (int o = 0; o < NCLS; ++o) {
                nb[o] = expf(nb[o] - m);
                ssum += nb[o];
            }
            const float inv = 1.0f / ssum;
#pragma unroll
            for (int o = 0; o < NCLS; ++o) {
                const float ci = nb[o] * inv;
#pragma unroll
                for (int q = 0; q < 4; ++q) {
                    float4 uv = u4[o * 4 + q];
                    sd[o][4 * q] += ci * uv.x;
                    sd[o][4 * q + 1] += ci * uv.y;
                    sd[o][4 * q + 2] += ci * uv.z;
                    sd[o][4 * q + 3] += ci * uv.w;
                }
            }
        }
        // s_v is fully read above before any thread rewrites it:
        __syncthreads();
        reduce_squash(sd);
    }

    // ---- heads: t < NCLS computes 26 logits + log_softmax ----
    if (t < NCLS) {
        const float* vv = s_v + t * FD;
        float lg[NREL + 1];
#pragma unroll 4
        for (int r = 0; r < NREL; ++r) {
            float a = pred_b[r];
#pragma unroll
            for (int d = 0; d < FD; ++d) a += vv[d] * pred_w[r * FD + d];
            lg[r] = a;
        }
        {
            float a = eos_b[0];
#pragma unroll
            for (int d = 0; d < FD; ++d) a += vv[d] * eos_w[d];
            lg[NREL] = a;
        }
        float m = lg[0];
#pragma unroll
        for (int k = 1; k <= NREL; ++k) m = fmaxf(m, lg[k]);
        float s = 0.0f;
#pragma unroll
        for (int k = 0; k <= NREL; ++k) s += expf(lg[k] - m);
        const float ls = m + logf(s);
#pragma unroll
        for (int k = 0; k <= NREL; ++k)
            out[((size_t)b * NCLS + t) * (NREL + 1) + k] = lg[k] - ls;
    }
}

// =====================================================================
extern "C" void kernel_launch(void* const* d_in, const int* in_sizes, int n_in,
                              void* d_out, int out_size) {
    const float* input   = (const float*)d_in[0];
    const float* conv1_w = (const float*)d_in[1];
    const float* conv1_b = (const float*)d_in[2];
    const float* prim_w  = (const float*)d_in[3];
    const float* prim_b  = (const float*)d_in[4];
    const float* caps_w  = (const float*)d_in[5];
    const float* b_route = (const float*)d_in[6];
    const float* pred_w  = (const float*)d_in[7];
    const float* pred_b  = (const float*)d_in[8];
    const float* eos_w   = (const float*)d_in[9];
    const float* eos_b   = (const float*)d_in[10];
    float* out = (float*)d_out;

    uint32_t *infp, *bf2p;
    uint4 *w1fp, *w2fp;
    float *prim4, *upp;
    cudaGetSymbolAddress((void**)&infp, g_inf);
    cudaGetSymbolAddress((void**)&w1fp, g_w1f);
    cudaGetSymbolAddress((void**)&w2fp, g_w2f);
    cudaGetSymbolAddress((void**)&bf2p, g_bf2);
    cudaGetSymbolAddress((void**)&prim4, g_prim4);
    cudaGetSymbolAddress((void**)&upp, g_up);

    const size_t NINF = (size_t)BATCH * IH * 10 * 1024;
    const int SMEM_C1 = 2 * 2560 * 16;          // 80KB
    const int SMEM_RT = RSM_TOT * 4;            // ~72KB

    cudaFuncSetAttribute(conv1_mma, cudaFuncAttributeMaxDynamicSharedMemorySize,
                         SMEM_C1);
    cudaFuncSetAttribute(route_all, cudaFuncAttributeMaxDynamicSharedMemorySize,
                         SMEM_RT);

    prep_inf<<<(unsigned)((NINF + 255) / 256), 256>>>(input, infp);
    prep_c1wf<<<(300 * 16 * 32 * 4 + 255) / 256, 256>>>(conv1_w,
                                                        (uint32_t*)w1fp);
    prep_c2wf<<<(NS2 * 16 * 32 * 4 + 255) / 256, 256>>>(prim_w,
                                                        (uint32_t*)w2fp);
    conv1_mma<<<dim3(2, OH1, BATCH), 256, SMEM_C1>>>(infp, w1fp, conv1_b,
                                                     (u16*)bf2p);
    conv2_mma<<<dim3(2, BATCH, KSPLIT), 256>>>(bf2p, w2fp, prim_b, prim4);
    squash_predict_kernel<<<dim3(NCAP, BATCH), 80>>>(prim4, caps_w, upp);
    route_all<<<BATCH, 256, SMEM_RT>>>(upp, b_route, pred_w, pred_b,
                                       eos_w, eos_b, out);
}

// round 16
// speedup vs baseline: 1.2385x; 1.0411x over previous
#include <cuda_runtime.h>
#include <cuda_fp16.h>
#include <math.h>
#include <stdint.h>

typedef unsigned short u16;

// ---------------- problem constants ----------------
#define BATCH 32
#define IH 120
#define IW 640
#define OH1 90            // only rows 0..89 consumed by conv2
#define NCAP 3456
#define NCLS 5
#define FD 16
#define JD 80
#define NREL 25
#define K1 4800
#define K2 25600
#define NPOS 108
#define KSPLIT 8
#define NS2 1600          // K2/16 k16-slices

// ---------------- device scratch ----------------
// conv1 B operand, PAIRED fragment order:
// [(b*120+row)*5 + spair][nf 0..15][lane][4u32]  (w<2: slice 2sp, else 2sp+1)
__device__ uint32_t g_inf[(size_t)BATCH * IH * 10 * 1024];
// conv1 A operand, fragment order: [step*16+rb][lane][4 u32]
__device__ uint4 g_w1f[300 * 16 * 32];
// conv2 A operand, fragment order: [s2*16+rb][lane][4 u32]
__device__ uint4 g_w2f[NS2 * 16 * 32];
// conv2 B operand (conv1 output), fragment order: [b][s2][nf][lane][2u32]
__device__ uint32_t g_bf2[(size_t)BATCH * NS2 * 16 * 64];
__device__ float g_prim4[KSPLIT][BATCH * 256 * NPOS];
__device__ __half g_up[(size_t)BATCH * NCAP * JD];

// ---------------- helpers ----------------
__device__ __forceinline__ void mma16816(float* c, const uint32_t* a,
                                         const uint32_t* b) {
    asm volatile(
        "mma.sync.aligned.m16n8k16.row.col.f32.f16.f16.f32 "
        "{%0,%1,%2,%3}, {%4,%5,%6,%7}, {%8,%9}, {%0,%1,%2,%3};"
        : "+f"(c[0]), "+f"(c[1]), "+f"(c[2]), "+f"(c[3])
        : "r"(a[0]), "r"(a[1]), "r"(a[2]), "r"(a[3]), "r"(b[0]), "r"(b[1]));
}
__device__ __forceinline__ void cp16(uint32_t dst, const void* src) {
    asm volatile("cp.async.ca.shared.global [%0], [%1], 16;"
                 :: "r"(dst), "l"(src));
}
__device__ __forceinline__ void cp_commit() {
    asm volatile("cp.async.commit_group;");
}
__device__ __forceinline__ void cp_wait0() {
    asm volatile("cp.async.wait_group 0;");
}
__device__ __forceinline__ uint32_t pack2h(float v0, float v1) {
    __half2 h = __floats2half2_rn(v0, v1);
    return *(uint32_t*)&h;
}
__device__ __forceinline__ void unpack8(uint4 v, float* f) {
    const __half2* h = (const __half2*)&v;
#pragma unroll
    for (int q = 0; q < 4; ++q) {
        float2 t = __half22float2(h[q]);
        f[2 * q] = t.x;
        f[2 * q + 1] = t.y;
    }
}

// =====================================================================
// prep: input -> conv1 B PAIRED fragment order.
// idx: w(0..3), lane, nf j, spair, rowb.
// slice s = 2*sp + (w>>1), word ww = w&1;
// col0 = 4*(8*j+grp) + 16*s + 2*tig + 8*ww
// =====================================================================
__global__ void prep_inf(const float* __restrict__ in,
                         uint32_t* __restrict__ inf) {
    size_t idx = (size_t)blockIdx.x * 256 + threadIdx.x;
    if (idx >= (size_t)BATCH * IH * 10 * 1024) return;
    int w = idx & 3;
    int lane = (idx >> 2) & 31;
    int j = (idx >> 7) & 15;
    size_t t = idx >> 11;
    int sp = (int)(t % 5);
    size_t rowb = t / 5;
    int grp = lane >> 2, tig = lane & 3;
    int s = 2 * sp + (w >> 1);
    int ww = w & 1;
    int col0 = 4 * (8 * j + grp) + 16 * s + 2 * tig + 8 * ww;
    float v0 = (col0 < IW) ? in[rowb * IW + col0] : 0.0f;
    float v1 = (col0 + 1 < IW) ? in[rowb * IW + col0 + 1] : 0.0f;
    inf[idx] = pack2h(v0, v1);
}

// =====================================================================
// prep conv1 weights -> A fragment order.
// =====================================================================
__global__ void prep_c1wf(const float* __restrict__ w,
                          uint32_t* __restrict__ w1f) {
    int idx = blockIdx.x * 256 + threadIdx.x;   // 614400
    if (idx >= 300 * 16 * 32 * 4) return;
    int j = idx & 3;
    int lane = (idx >> 2) & 31;
    int rb = (idx >> 7) & 15;
    int step = idx >> 11;
    int grp = lane >> 2, tig = lane & 3;
    int c = rb * 16 + grp + (j & 1) * 8;
    int kk = 2 * tig + (j >> 1) * 8;
    int kh = step / 10, kws = step - 10 * kh;
    int kg = kh * 160 + kws * 16 + kk;
    w1f[idx] = pack2h(w[(size_t)c * K1 + kg], w[(size_t)c * K1 + kg + 1]);
}

// =====================================================================
// prep conv2 weights -> A fragment order [s2][rb][lane][j].
// =====================================================================
__global__ void prep_c2wf(const float* __restrict__ w2,
                          uint32_t* __restrict__ w2f) {
    int idx = blockIdx.x * 256 + threadIdx.x;   // 3,276,800
    if (idx >= NS2 * 16 * 32 * 4) return;
    int j = idx & 3;
    int lane = (idx >> 2) & 31;
    int rb = (idx >> 7) & 15;
    int s2 = idx >> 11;
    int grp = lane >> 2, tig = lane & 3;
    int c2 = rb * 16 + grp + (j & 1) * 8;
    int k0 = s2 * 16 + 2 * tig + (j >> 1) * 8;
    float v0 = w2[((size_t)c2 * 256 + (k0 & 255)) * 100 + (k0 >> 8)];
    float v1 = w2[((size_t)c2 * 256 + ((k0 + 1) & 255)) * 100 + ((k0 + 1) >> 8)];
    w2f[idx] = pack2h(v0, v1);
}

// =====================================================================
// conv1 via HMMA, paired-B fragment order.
// CTA = (mt, oh, b): M128 x N128(ow) x K4800. 8 warps 2(M)x4(N),
// warp 64x32, 2 CTAs/SM. A: kh-row cp.async double buffer (80KB).
// B: LDG.128 per slice-PAIR (halved B wavefronts).
// Epilogue -> conv2-B-fragment order fp16.
// =====================================================================
__global__ __launch_bounds__(256, 2)
void conv1_mma(const uint32_t* __restrict__ inf, const uint4* __restrict__ w1f,
               const float* __restrict__ bias, u16* __restrict__ bf2) {
    extern __shared__ uint4 sA[];   // [2][2560]

    const int tid = threadIdx.x;
    const int wid = tid >> 5, lane = tid & 31;
    const int grp = lane >> 2, tig = lane & 3;
    const int wm = wid >> 2, wn = wid & 3;
    const int mt = blockIdx.x, oh = blockIdx.y, b = blockIdx.z;

    float acc[4][4][4] = {};

    const uint32_t sA0 = (uint32_t)__cvta_generic_to_shared(&sA[0]);

    auto stageA = [&](int it, int stg) {
#pragma unroll
        for (int r = 0; r < 10; ++r) {
            const int c = tid + (r << 8);
            const int slice = c >> 8;
            const int rbl = (c >> 5) & 7;
            const int ln = c & 31;
            const int step = it * 10 + slice;
            cp16(sA0 + (stg * 2560 + c) * 16,
                 w1f + ((step * 16 + mt * 8 + rbl) * 32 + ln));
        }
        cp_commit();
    };

    stageA(0, 0);
    cp_wait0();
    __syncthreads();

    const uint4* infq = (const uint4*)inf;

    for (int it = 0; it < 30; ++it) {                  // it = kh
        const int stg = it & 1;
        if (it < 29) stageA(it + 1, stg ^ 1);

        const size_t rowb = (size_t)b * IH + oh + it;
        // paired B: ((rowb*5 + sp)*16 + wn*4 + nf)*32 + lane (uint4 units)
        const uint4* bb = infq + (rowb * 5 * 16 + wn * 4) * 32 + lane;
#pragma unroll
        for (int sp = 0; sp < 5; ++sp) {
            uint4 bp[4];
#pragma unroll
            for (int nf = 0; nf < 4; ++nf)
                bp[nf] = bb[(sp * 16 + nf) * 32];
            uint4 af0[4], af1[4];
#pragma unroll
            for (int mf = 0; mf < 4; ++mf) {
                af0[mf] = sA[stg * 2560 + (2 * sp) * 256 + (wm * 4 + mf) * 32 +
                             lane];
                af1[mf] = sA[stg * 2560 + (2 * sp + 1) * 256 +
                             (wm * 4 + mf) * 32 + lane];
            }
#pragma unroll
            for (int mf = 0; mf < 4; ++mf)
#pragma unroll
                for (int nf = 0; nf < 4; ++nf) {
                    mma16816(acc[mf][nf], (const uint32_t*)&af0[mf],
                             (const uint32_t*)&bp[nf]);        // words x,y
                    mma16816(acc[mf][nf], (const uint32_t*)&af1[mf],
                             ((const uint32_t*)&bp[nf]) + 2);  // words z,w
                }
        }
        cp_wait0();
        __syncthreads();
    }

    // epilogue: bias + relu -> fp16, conv2-B-fragment order.
    const int ohh = oh / 10, kh2 = oh - 10 * ohh;
#pragma unroll
    for (int mf = 0; mf < 4; ++mf) {
#pragma unroll
        for (int nf = 0; nf < 4; ++nf) {
#pragma unroll
            for (int i = 0; i < 4; ++i) {
                const int c = mt * 128 + wm * 64 + mf * 16 + grp + (i >> 1) * 8;
                const int ow = wn * 32 + nf * 8 + 2 * tig + (i & 1);
                if (ow < 120) {
                    float v = fmaxf(acc[mf][nf][i] + bias[c], 0.0f);
                    const int pos = ohh * 12 + ow / 10;
                    const int r = kh2 * 10 + (ow % 10);
                    const int s2 = r * 16 + mt * 8 + wm * 4 + mf;
                    const int lane2 = (pos & 7) * 4 + (grp >> 1);
                    const size_t o =
                        ((((size_t)b * NS2 + s2) * 16 + (pos >> 3)) * 32 +
                         lane2) * 4 + (i >> 1) * 2 + (grp & 1);
                    bf2[o] = __half_as_ushort(__float2half_rn(v));
                }
            }
        }
    }
}

// =====================================================================
// conv2 via HMMA, barrier-free fragment-order (unchanged).
// =====================================================================
__global__ __launch_bounds__(256, 2)
void conv2_mma(const uint32_t* __restrict__ bf2, const uint4* __restrict__ w2f,
               const float* __restrict__ pb, float* __restrict__ prim4) {
    const int tid = threadIdx.x;
    const int wid = tid >> 5, lane = tid & 31;
    const int grp = lane >> 2, tig = lane & 3;
    const int wm = wid >> 2, wn = wid & 3;
    const int mt = blockIdx.x, b = blockIdx.y, ks = blockIdx.z;

    float acc[4][4][4] = {};

    const int NSL = NS2 / KSPLIT;   // 200
    const uint4* Ab = w2f + ((size_t)(ks * NSL) * 16 + mt * 8 + wm * 4) * 32 +
                      lane;
    const uint32_t* Bb = bf2 + (((size_t)b * NS2 + ks * NSL) * 16 + wn * 4) *
                         64 + lane * 2;

    for (int s = 0; s < NSL; ++s) {
        uint2 bfr[4];
#pragma unroll
        for (int nf = 0; nf < 4; ++nf)
            bfr[nf] = *(const uint2*)(Bb + (size_t)s * 1024 + nf * 64);
        uint4 af[4];
#pragma unroll
        for (int mf = 0; mf < 4; ++mf)
            af[mf] = Ab[((size_t)s * 16 + mf) * 32];
#pragma unroll
        for (int mf = 0; mf < 4; ++mf)
#pragma unroll
            for (int nf = 0; nf < 4; ++nf)
                mma16816(acc[mf][nf], (const uint32_t*)&af[mf],
                         (const uint32_t*)&bfr[nf]);
    }

    float* outp = prim4 + (size_t)ks * (BATCH * 256 * NPOS);
#pragma unroll
    for (int mf = 0; mf < 4; ++mf) {
#pragma unroll
        for (int nf = 0; nf < 4; ++nf) {
#pragma unroll
            for (int i = 0; i < 4; ++i) {
                const int c2 = mt * 128 + wm * 64 + mf * 16 + grp + (i >> 1) * 8;
                const int n = (wn * 4 + nf) * 8 + 2 * tig + (i & 1);
                if (n < NPOS) {
                    float v = acc[mf][nf][i] + (ks == 0 ? pb[c2] : 0.0f);
                    outp[((size_t)b * 256 + c2) * NPOS + n] = v;
                }
            }
        }
    }
}

// =====================================================================
// squash + caps prediction (sums KSPLIT conv2 partials), fp16 output
// =====================================================================
__global__ void squash_predict_kernel(const float* __restrict__ prim4,
                                      const float* __restrict__ caps_w,
                                      __half* __restrict__ up) {
    __shared__ float su[8];
    __shared__ float sfac;
    const int i = blockIdx.x;
    const int b = blockIdx.y;
    const int g = i / NPOS;
    const int p = i - g * NPOS;
    const int t = threadIdx.x;
    const int SL = BATCH * 256 * NPOS;

    if (t < 8) {
        size_t o = ((size_t)b * 256 + g * 8 + t) * NPOS + p;
        float acc = 0.0f;
#pragma unroll
        for (int q = 0; q < KSPLIT; ++q) acc += prim4[o + (size_t)q * SL];
        su[t] = acc;
    }
    __syncthreads();
    if (t == 0) {
        float l2 = 0.0f;
#pragma unroll
        for (int d = 0; d < 8; ++d) l2 += su[d] * su[d];
        sfac = sqrtf(l2) / (1.0f + l2);
    }
    __syncthreads();
    const float f = sfac;
    const float* cw = caps_w + (size_t)i * 8 * JD + t;
    float a = 0.0f;
#pragma unroll
    for (int d = 0; d < 8; ++d) a += su[d] * f * cw[d * JD];
    up[((size_t)b * NCAP + i) * JD + t] = __float2half_rn(a);
}

// =====================================================================
// FUSED routing (4 iterations) + heads. One CTA per batch element.
// up is fp16 (half traffic). bb state in smem.
// =====================================================================
#define RSM_BB 0
#define RSM_FIN (NCAP * NCLS)
#define RSM_FAC (RSM_FIN + 80)
#define RSM_PART (RSM_FAC + 8)
#define RSM_V (RSM_PART + 8 * 80)
#define RSM_TOT (RSM_V + 80)

__global__ __launch_bounds__(256, 1)
void route_all(const __half* __restrict__ up, const float* __restrict__ b_route,
               const float* __restrict__ pred_w,
               const float* __restrict__ pred_b,
               const float* __restrict__ eos_w,
               const float* __restrict__ eos_b, float* __restrict__ out) {
    extern __shared__ float rs[];
    float* s_bb = rs + RSM_BB;
    float* s_fin = rs + RSM_FIN;
    float* s_fac = rs + RSM_FAC;
    float* s_part = rs + RSM_PART;
    float* s_v = rs + RSM_V;

    const int b = blockIdx.x;
    const int t = threadIdx.x;
    const int lane = t & 31, wid = t >> 5;
    const __half* upb = up + (size_t)b * NCAP * JD;

    auto reduce_squash = [&](float sd[NCLS][FD]) {
#pragma unroll
        for (int o = 0; o < NCLS; ++o)
#pragma unroll
            for (int d = 0; d < FD; ++d)
#pragma unroll
                for (int off = 16; off; off >>= 1)
                    sd[o][d] += __shfl_down_sync(0xffffffffu, sd[o][d], off);
        if (lane == 0)
#pragma unroll
            for (int o = 0; o < NCLS; ++o)
#pragma unroll
                for (int d = 0; d < FD; ++d)
                    s_part[wid * 80 + o * FD + d] = sd[o][d];
        __syncthreads();
        if (t < 80) {
            float tot = 0.0f;
#pragma unroll
            for (int w = 0; w < 8; ++w) tot += s_part[w * 80 + t];
            s_fin[t] = tot;
        }
        __syncthreads();
        if (t < NCLS) {
            float l2 = 0.0f;
#pragma unroll
            for (int d = 0; d < FD; ++d) {
                float x = s_fin[t * FD + d];
                l2 += x * x;
            }
            s_fac[t] = sqrtf(l2) / (1.0f + l2);
        }
        __syncthreads();
        if (t < 80) s_v[t] = s_fin[t] * s_fac[t / FD];
        __syncthreads();
    };

    // ---- iteration 0 ----
    {
        float sd[NCLS][FD] = {};
        for (int i = t; i < NCAP; i += 256) {
            float br[NCLS];
#pragma unroll
            for (int o = 0; o < NCLS; ++o) br[o] = b_route[i * NCLS + o];
            float m = br[0];
#pragma unroll
            for (int o = 1; o < NCLS; ++o) m = fmaxf(m, br[o]);
            float ssum = 0.0f;
            float ce[NCLS];
#pragma unroll
            for (int o = 0; o < NCLS; ++o) {
                ce[o] = expf(br[o] - m);
                ssum += ce[o];
            }
            const float inv = 1.0f / ssum;
            const uint4* u4 = (const uint4*)(upb + (size_t)i * JD);
#pragma unroll
            for (int o = 0; o < NCLS; ++o) {
                float uo[FD];
                unpack8(u4[o * 2], uo);
                unpack8(u4[o * 2 + 1], uo + 8);
                const float ci = ce[o] * inv;
#pragma unroll
                for (int d = 0; d < FD; ++d) sd[o][d] += ci * uo[d];
            }
        }
        reduce_squash(sd);
    }

    // ---- 3 routing iterations ----
    for (int it = 0; it < 3; ++it) {
        float sd[NCLS][FD] = {};
        for (int i = t; i < NCAP; i += 256) {
            const uint4* u4 = (const uint4*)(upb + (size_t)i * JD);
            float uall[NCLS][FD];
            float nb[NCLS];
#pragma unroll
            for (int o = 0; o < NCLS; ++o) {
                unpack8(u4[o * 2], uall[o]);
                unpack8(u4[o * 2 + 1], uall[o] + 8);
                float dot = 0.0f;
#pragma unroll
                for (int d = 0; d < FD; ++d) dot += uall[o][d] * s_v[o * FD + d];
                float prev = (it == 0) ? b_route[i * NCLS + o]
                                       : s_bb[i * NCLS + o];
                nb[o] = prev + dot;
                s_bb[i * NCLS + o] = nb[o];
            }
            float m = nb[0];
#pragma unroll
            for (int o = 1; o < NCLS; ++o) m = fmaxf(m, nb[o]);
            float ssum = 0.0f;
#pragma unroll
            for (int o = 0; o < NCLS; ++o) {
                nb[o] = expf(nb[o] - m);
                ssum += nb[o];
            }
            const float inv = 1.0f / ssum;
#pragma unroll
            for (int o = 0; o < NCLS; ++o) {
                const float ci = nb[o] * inv;
#pragma unroll
                for (int d = 0; d < FD; ++d) sd[o][d] += ci * uall[o][d];
            }
        }
        __syncthreads();
        reduce_squash(sd);
    }

    // ---- heads ----
    if (t < NCLS) {
        const float* vv = s_v + t * FD;
        float lg[NREL + 1];
#pragma unroll 4
        for (int r = 0; r < NREL; ++r) {
            float a = pred_b[r];
#pragma unroll
            for (int d = 0; d < FD; ++d) a += vv[d] * pred_w[r * FD + d];
            lg[r] = a;
        }
        {
            float a = eos_b[0];
#pragma unroll
            for (int d = 0; d < FD; ++d) a += vv[d] * eos_w[d];
            lg[NREL] = a;
        }
        float m = lg[0];
#pragma unroll
        for (int k = 1; k <= NREL; ++k) m = fmaxf(m, lg[k]);
        float s = 0.0f;
#pragma unroll
        for (int k = 0; k <= NREL; ++k) s += expf(lg[k] - m);
        const float ls = m + logf(s);
#pragma unroll
        for (int k = 0; k <= NREL; ++k)
            out[((size_t)b * NCLS + t) * (NREL + 1) + k] = lg[k] - ls;
    }
}

// =====================================================================
extern "C" void kernel_launch(void* const* d_in, const int* in_sizes, int n_in,
                              void* d_out, int out_size) {
    const float* input   = (const float*)d_in[0];
    const float* conv1_w = (const float*)d_in[1];
    const float* conv1_b = (const float*)d_in[2];
    const float* prim_w  = (const float*)d_in[3];
    const float* prim_b  = (const float*)d_in[4];
    const float* caps_w  = (const float*)d_in[5];
    const float* b_route = (const float*)d_in[6];
    const float* pred_w  = (const float*)d_in[7];
    const float* pred_b  = (const float*)d_in[8];
    const float* eos_w   = (const float*)d_in[9];
    const float* eos_b   = (const float*)d_in[10];
    float* out = (float*)d_out;

    uint32_t *infp, *bf2p;
    uint4 *w1fp, *w2fp;
    float* prim4;
    __half* upp;
    cudaGetSymbolAddress((void**)&infp, g_inf);
    cudaGetSymbolAddress((void**)&w1fp, g_w1f);
    cudaGetSymbolAddress((void**)&w2fp, g_w2f);
    cudaGetSymbolAddress((void**)&bf2p, g_bf2);
    cudaGetSymbolAddress((void**)&prim4, g_prim4);
    cudaGetSymbolAddress((void**)&upp, g_up);

    const size_t NINF = (size_t)BATCH * IH * 10 * 1024;
    const int SMEM_C1 = 2 * 2560 * 16;          // 80KB
    const int SMEM_RT = RSM_TOT * 4;            // ~72KB

    cudaFuncSetAttribute(conv1_mma, cudaFuncAttributeMaxDynamicSharedMemorySize,
                         SMEM_C1);
    cudaFuncSetAttribute(route_all, cudaFuncAttributeMaxDynamicSharedMemorySize,
                         SMEM_RT);

    prep_inf<<<(unsigned)((NINF + 255) / 256), 256>>>(input, infp);
    prep_c1wf<<<(300 * 16 * 32 * 4 + 255) / 256, 256>>>(conv1_w,
                                                        (uint32_t*)w1fp);
    prep_c2wf<<<(NS2 * 16 * 32 * 4 + 255) / 256, 256>>>(prim_w,
                                                        (uint32_t*)w2fp);
    conv1_mma<<<dim3(2, OH1, BATCH), 256, SMEM_C1>>>(infp, w1fp, conv1_b,
                                                     (u16*)bf2p);
    conv2_mma<<<dim3(2, BATCH, KSPLIT), 256>>>(bf2p, w2fp, prim_b, prim4);
    squash_predict_kernel<<<dim3(NCAP, BATCH), 80>>>(prim4, caps_w, upp);
    route_all<<<BATCH, 256, SMEM_RT>>>(upp, b_route, pred_w, pred_b,
                                       eos_w, eos_b, out);
}